// round 3
// baseline (speedup 1.0000x reference)
#include <cuda_runtime.h>
#include <math.h>

// Problem dims (fixed)
#define Bn 8
#define Tn 1024
#define Cn 1024
#define NHh 16
#define HDd 64
#define FFf 4096
#define MROWS (Bn*Tn)   // 8192

// ---------------- scratch (static device globals; no allocation) -------------
// __align__(16) is REQUIRED: these buffers are accessed via float4; device
// globals otherwise only guarantee 4-byte alignment.
static __device__ __align__(16) float g_h  [MROWS*Cn];          // 32 MB
static __device__ __align__(16) float g_qkv[MROWS*3*Cn];        // 96 MB
static __device__ __align__(16) float g_y  [MROWS*Cn];          // 32 MB
static __device__ __align__(16) float g_x1 [MROWS*Cn];          // 32 MB
static __device__ __align__(16) float g_ff [(size_t)MROWS*FFf]; // 128 MB

// ---------------- LayerNorm ---------------------------------------------------
__global__ __launch_bounds__(256)
void ln_kernel(const float* __restrict__ x, const float* __restrict__ gamma,
               const float* __restrict__ beta, float* __restrict__ out)
{
    const int row = blockIdx.x;
    const float4* xr = reinterpret_cast<const float4*>(x + (size_t)row * Cn);
    float4 v = xr[threadIdx.x];                       // 256 thr * 4 = 1024
    float s  = v.x + v.y + v.z + v.w;
    float ss = v.x*v.x + v.y*v.y + v.z*v.z + v.w*v.w;
    #pragma unroll
    for (int o = 16; o > 0; o >>= 1) {
        s  += __shfl_xor_sync(0xffffffffu, s,  o);
        ss += __shfl_xor_sync(0xffffffffu, ss, o);
    }
    __shared__ float rs[8], rss[8];
    const int w = threadIdx.x >> 5;
    if ((threadIdx.x & 31) == 0) { rs[w] = s; rss[w] = ss; }
    __syncthreads();
    if (threadIdx.x < 32) {
        float ts  = (threadIdx.x < 8) ? rs[threadIdx.x]  : 0.f;
        float tss = (threadIdx.x < 8) ? rss[threadIdx.x] : 0.f;
        #pragma unroll
        for (int o = 4; o > 0; o >>= 1) {
            ts  += __shfl_xor_sync(0xffffffffu, ts,  o);
            tss += __shfl_xor_sync(0xffffffffu, tss, o);
        }
        if (threadIdx.x == 0) {
            float mean = ts * (1.0f/Cn);
            float var  = tss * (1.0f/Cn) - mean*mean;
            rs[0]  = mean;
            rss[0] = rsqrtf(var + 1e-5f);
        }
    }
    __syncthreads();
    const float mean = rs[0], rstd = rss[0];
    const float4 g4 = reinterpret_cast<const float4*>(gamma)[threadIdx.x];
    const float4 b4 = reinterpret_cast<const float4*>(beta )[threadIdx.x];
    float4 o4;
    o4.x = (v.x - mean)*rstd*g4.x + b4.x;
    o4.y = (v.y - mean)*rstd*g4.y + b4.y;
    o4.z = (v.z - mean)*rstd*g4.z + b4.z;
    o4.w = (v.w - mean)*rstd*g4.w + b4.w;
    reinterpret_cast<float4*>(out + (size_t)row*Cn)[threadIdx.x] = o4;
}

// ---------------- SGEMM: C = act(A @ W + bias [+ R]) --------------------------
// A: [M,K] row-major, W: [K,N] row-major, C/R: [M,N]. 128x128x16 tile, 256 thr.
template<bool RELU, bool RESID>
__global__ __launch_bounds__(256)
void sgemm_kernel(const float* __restrict__ A, const float* __restrict__ W,
                  const float* __restrict__ bias, const float* __restrict__ R,
                  float* __restrict__ Cmat, int M, int N, int K)
{
    __shared__ float As[16][132];   // stored transposed: As[k][m]
    __shared__ float Ws[16][132];   // Ws[k][n]
    const int tid = threadIdx.x;
    const int tr = tid >> 4, tc = tid & 15;
    const int bm = blockIdx.y << 7, bn = blockIdx.x << 7;

    float acc[8][8];
    #pragma unroll
    for (int i = 0; i < 8; ++i)
        #pragma unroll
        for (int j = 0; j < 8; ++j) acc[i][j] = 0.f;

    const int ar0 = tid >> 2;            // 0..63
    const int ak0 = (tid & 3) << 2;      // 0,4,8,12
    const int wk0 = tid >> 5;            // 0..7
    const int wn0 = (tid & 31) << 2;     // 0..124

    for (int k0 = 0; k0 < K; k0 += 16) {
        #pragma unroll
        for (int u = 0; u < 2; ++u) {
            const int row = ar0 + u*64;
            const float4 t = *reinterpret_cast<const float4*>(
                &A[(size_t)(bm + row)*K + k0 + ak0]);
            As[ak0+0][row] = t.x; As[ak0+1][row] = t.y;
            As[ak0+2][row] = t.z; As[ak0+3][row] = t.w;
        }
        #pragma unroll
        for (int u = 0; u < 2; ++u) {
            const int kr = wk0 + u*8;
            *reinterpret_cast<float4*>(&Ws[kr][wn0]) =
                *reinterpret_cast<const float4*>(&W[(size_t)(k0 + kr)*N + bn + wn0]);
        }
        __syncthreads();
        #pragma unroll
        for (int k = 0; k < 16; ++k) {
            float a[8], w[8];
            *reinterpret_cast<float4*>(&a[0]) = *reinterpret_cast<const float4*>(&As[k][tr*4]);
            *reinterpret_cast<float4*>(&a[4]) = *reinterpret_cast<const float4*>(&As[k][64 + tr*4]);
            *reinterpret_cast<float4*>(&w[0]) = *reinterpret_cast<const float4*>(&Ws[k][tc*4]);
            *reinterpret_cast<float4*>(&w[4]) = *reinterpret_cast<const float4*>(&Ws[k][64 + tc*4]);
            #pragma unroll
            for (int i = 0; i < 8; ++i)
                #pragma unroll
                for (int j = 0; j < 8; ++j)
                    acc[i][j] += a[i] * w[j];
        }
        __syncthreads();
    }

    #pragma unroll
    for (int i = 0; i < 8; ++i) {
        const int r = bm + ((i < 4) ? (tr*4 + i) : (64 + tr*4 + (i - 4)));
        #pragma unroll
        for (int jj = 0; jj < 2; ++jj) {
            const int c0 = bn + ((jj == 0) ? (tc*4) : (64 + tc*4));
            const float4 bb = *reinterpret_cast<const float4*>(&bias[c0]);
            float4 o;
            o.x = acc[i][jj*4+0] + bb.x;
            o.y = acc[i][jj*4+1] + bb.y;
            o.z = acc[i][jj*4+2] + bb.z;
            o.w = acc[i][jj*4+3] + bb.w;
            if (RESID) {
                const float4 rr = *reinterpret_cast<const float4*>(&R[(size_t)r*N + c0]);
                o.x += rr.x; o.y += rr.y; o.z += rr.z; o.w += rr.w;
            }
            if (RELU) {
                o.x = fmaxf(o.x, 0.f); o.y = fmaxf(o.y, 0.f);
                o.z = fmaxf(o.z, 0.f); o.w = fmaxf(o.w, 0.f);
            }
            *reinterpret_cast<float4*>(&Cmat[(size_t)r*N + c0]) = o;
        }
    }
}

// ---------------- Flash attention (64q x 32k tiles, online softmax) -----------
__global__ __launch_bounds__(256)
void attn_kernel(const float* __restrict__ qkv, const int* __restrict__ seq_ls,
                 float* __restrict__ y)
{
    const int qt = blockIdx.x;   // 0..15 (q tile of 64)
    const int h  = blockIdx.y;   // head
    const int b  = blockIdx.z;   // batch

    __shared__ float Qs[64][68];
    __shared__ float Ks[32][68];
    __shared__ float Vs[32][68];
    __shared__ float Ss[64][33];
    __shared__ float m_s[64], l_s[64], fac[64];

    const int tid = threadIdx.x;
    const int ty = tid >> 4, tx = tid & 15;
    const int seq_l = seq_ls[b];

    // Load + pre-scale Q tile (64x64)
    for (int i = tid; i < 64*16; i += 256) {
        const int r = i >> 4, cq = (i & 15) << 2;
        const int bt = b*Tn + qt*64 + r;
        float4 v = *reinterpret_cast<const float4*>(
            &qkv[(size_t)bt*3*Cn + h*HDd + cq]);
        v.x *= 0.125f; v.y *= 0.125f; v.z *= 0.125f; v.w *= 0.125f;
        *reinterpret_cast<float4*>(&Qs[r][cq]) = v;
    }
    if (tid < 64) { m_s[tid] = -3.0e38f; l_s[tid] = 0.f; }

    float acc[4][4];
    #pragma unroll
    for (int i = 0; i < 4; ++i)
        #pragma unroll
        for (int j = 0; j < 4; ++j) acc[i][j] = 0.f;

    const int r0 = ty*4;
    const int nkt = (seq_l + 31) >> 5;
    __syncthreads();

    for (int kb = 0; kb < nkt; ++kb) {
        const int kbase = kb << 5;
        // Load K,V tiles (32x64 each)
        for (int i = tid; i < 32*16; i += 256) {
            const int r = i >> 4, cq = (i & 15) << 2;
            const int bt = b*Tn + kbase + r;
            *reinterpret_cast<float4*>(&Ks[r][cq]) =
                *reinterpret_cast<const float4*>(&qkv[(size_t)bt*3*Cn + Cn   + h*HDd + cq]);
            *reinterpret_cast<float4*>(&Vs[r][cq]) =
                *reinterpret_cast<const float4*>(&qkv[(size_t)bt*3*Cn + 2*Cn + h*HDd + cq]);
        }
        __syncthreads();

        // S = Q K^T  (each thread: 4 q-rows x 2 k-cols)
        #pragma unroll
        for (int j = 0; j < 2; ++j) {
            const int c = (tx << 1) + j;
            float s0 = 0.f, s1 = 0.f, s2 = 0.f, s3 = 0.f;
            #pragma unroll
            for (int d4 = 0; d4 < 16; ++d4) {
                const float4 kv = *reinterpret_cast<const float4*>(&Ks[c][d4*4]);
                const float4 q0 = *reinterpret_cast<const float4*>(&Qs[r0+0][d4*4]);
                const float4 q1 = *reinterpret_cast<const float4*>(&Qs[r0+1][d4*4]);
                const float4 q2 = *reinterpret_cast<const float4*>(&Qs[r0+2][d4*4]);
                const float4 q3 = *reinterpret_cast<const float4*>(&Qs[r0+3][d4*4]);
                s0 += q0.x*kv.x + q0.y*kv.y + q0.z*kv.z + q0.w*kv.w;
                s1 += q1.x*kv.x + q1.y*kv.y + q1.z*kv.z + q1.w*kv.w;
                s2 += q2.x*kv.x + q2.y*kv.y + q2.z*kv.z + q2.w*kv.w;
                s3 += q3.x*kv.x + q3.y*kv.y + q3.z*kv.z + q3.w*kv.w;
            }
            const bool valid = (kbase + c) < seq_l;
            Ss[r0+0][c] = valid ? s0 : -1.0e30f;
            Ss[r0+1][c] = valid ? s1 : -1.0e30f;
            Ss[r0+2][c] = valid ? s2 : -1.0e30f;
            Ss[r0+3][c] = valid ? s3 : -1.0e30f;
        }
        __syncthreads();

        // Online softmax (one thread per query row)
        if (tid < 64) {
            const float m_old = m_s[tid];
            float mx = m_old;
            #pragma unroll
            for (int c = 0; c < 32; ++c) mx = fmaxf(mx, Ss[tid][c]);
            const float f = __expf(m_old - mx);
            float sum = 0.f;
            #pragma unroll
            for (int c = 0; c < 32; ++c) {
                const float p = __expf(Ss[tid][c] - mx);
                Ss[tid][c] = p;
                sum += p;
            }
            m_s[tid] = mx;
            l_s[tid] = l_s[tid] * f + sum;
            fac[tid] = f;
        }
        __syncthreads();

        // acc = acc*fac + P @ V   (each thread: 4 rows x 4 dims)
        const float f0 = fac[r0+0], f1 = fac[r0+1], f2 = fac[r0+2], f3 = fac[r0+3];
        #pragma unroll
        for (int j = 0; j < 4; ++j) {
            acc[0][j] *= f0; acc[1][j] *= f1; acc[2][j] *= f2; acc[3][j] *= f3;
        }
        #pragma unroll
        for (int k = 0; k < 32; ++k) {
            const float4 v4 = *reinterpret_cast<const float4*>(&Vs[k][tx*4]);
            const float p0 = Ss[r0+0][k], p1 = Ss[r0+1][k];
            const float p2 = Ss[r0+2][k], p3 = Ss[r0+3][k];
            acc[0][0] += p0*v4.x; acc[0][1] += p0*v4.y; acc[0][2] += p0*v4.z; acc[0][3] += p0*v4.w;
            acc[1][0] += p1*v4.x; acc[1][1] += p1*v4.y; acc[1][2] += p1*v4.z; acc[1][3] += p1*v4.w;
            acc[2][0] += p2*v4.x; acc[2][1] += p2*v4.y; acc[2][2] += p2*v4.z; acc[2][3] += p2*v4.w;
            acc[3][0] += p3*v4.x; acc[3][1] += p3*v4.y; acc[3][2] += p3*v4.z; acc[3][3] += p3*v4.w;
        }
        __syncthreads();
    }

    // O = acc / l ; write to y [BT, C] at head offset
    #pragma unroll
    for (int i = 0; i < 4; ++i) {
        const int r = r0 + i;
        const float inv = 1.0f / l_s[r];
        const int bt = b*Tn + qt*64 + r;
        float4 o;
        o.x = acc[i][0]*inv; o.y = acc[i][1]*inv;
        o.z = acc[i][2]*inv; o.w = acc[i][3]*inv;
        *reinterpret_cast<float4*>(&y[(size_t)bt*Cn + h*HDd + tx*4]) = o;
    }
}

// ---------------- launch ------------------------------------------------------
extern "C" void kernel_launch(void* const* d_in, const int* in_sizes, int n_in,
                              void* d_out, int out_size)
{
    const float* x      = (const float*)d_in[0];
    const int*   seq_ls = (const int*)  d_in[1];
    const float* ln1_g  = (const float*)d_in[2];
    const float* ln1_b  = (const float*)d_in[3];
    const float* w_qkv  = (const float*)d_in[4];
    const float* b_qkv  = (const float*)d_in[5];
    const float* w_proj = (const float*)d_in[6];
    const float* b_proj = (const float*)d_in[7];
    const float* ln2_g  = (const float*)d_in[8];
    const float* ln2_b  = (const float*)d_in[9];
    const float* w_fc   = (const float*)d_in[10];
    const float* b_fc   = (const float*)d_in[11];
    const float* w_fc2  = (const float*)d_in[12];
    const float* b_fc2  = (const float*)d_in[13];
    float* out = (float*)d_out;

    float *h, *qkv, *y, *x1, *ff;
    cudaGetSymbolAddress((void**)&h,   g_h);
    cudaGetSymbolAddress((void**)&qkv, g_qkv);
    cudaGetSymbolAddress((void**)&y,   g_y);
    cudaGetSymbolAddress((void**)&x1,  g_x1);
    cudaGetSymbolAddress((void**)&ff,  g_ff);

    // 1. LN1
    ln_kernel<<<MROWS, 256>>>(x, ln1_g, ln1_b, h);
    // 2. QKV projection
    sgemm_kernel<false,false><<<dim3(3*Cn/128, MROWS/128), 256>>>(
        h, w_qkv, b_qkv, nullptr, qkv, MROWS, 3*Cn, Cn);
    // 3. Attention
    attn_kernel<<<dim3(Tn/64, NHh, Bn), 256>>>(qkv, seq_ls, y);
    // 4. Output projection + residual(x)
    sgemm_kernel<false,true><<<dim3(Cn/128, MROWS/128), 256>>>(
        y, w_proj, b_proj, x, x1, MROWS, Cn, Cn);
    // 5. LN2
    ln_kernel<<<MROWS, 256>>>(x1, ln2_g, ln2_b, h);
    // 6. FC + ReLU
    sgemm_kernel<true,false><<<dim3(FFf/128, MROWS/128), 256>>>(
        h, w_fc, b_fc, nullptr, ff, MROWS, FFf, Cn);
    // 7. FC2 + residual(x1) -> out
    sgemm_kernel<false,true><<<dim3(Cn/128, MROWS/128), 256>>>(
        ff, w_fc2, b_fc2, x1, out, MROWS, Cn, FFf);
}

// round 7
// speedup vs baseline: 1.5737x; 1.5737x over previous
#include <cuda_runtime.h>
#include <cuda_bf16.h>
#include <cstdint>
#include <math.h>

// Problem dims (fixed)
#define Bn 8
#define Tn 1024
#define Cn 1024
#define NHh 16
#define HDd 64
#define FFf 4096
#define MROWS (Bn*Tn)   // 8192

// Weight offsets inside the packed transposed-weight buffers (elements)
#define OFF_QKV 0
#define OFF_PROJ (3*Cn*Cn)
#define OFF_FC   (OFF_PROJ + Cn*Cn)
#define OFF_FC2  (OFF_FC + (size_t)FFf*Cn)
#define WSUM     (OFF_FC2 + (size_t)Cn*FFf)

// ---------------- scratch (static device globals; no allocation) -------------
static __device__ __align__(16) float          g_qkv[(size_t)MROWS*3*Cn];  // 96 MB
static __device__ __align__(16) float          g_x1 [(size_t)MROWS*Cn];    // 32 MB
static __device__ __align__(16) __nv_bfloat16  g_ahi[(size_t)MROWS*Cn];
static __device__ __align__(16) __nv_bfloat16  g_alo[(size_t)MROWS*Cn];
static __device__ __align__(16) __nv_bfloat16  g_yhi[(size_t)MROWS*Cn];
static __device__ __align__(16) __nv_bfloat16  g_ylo[(size_t)MROWS*Cn];
static __device__ __align__(16) __nv_bfloat16  g_ffhi[(size_t)MROWS*FFf];
static __device__ __align__(16) __nv_bfloat16  g_fflo[(size_t)MROWS*FFf];
static __device__ __align__(16) __nv_bfloat16  g_whi[WSUM];
static __device__ __align__(16) __nv_bfloat16  g_wlo[WSUM];

// ---------------- small helpers ------------------------------------------------
__device__ __forceinline__ uint32_t smem_u32(const void* p) {
    uint32_t a;
    asm("{ .reg .u64 t; cvta.to.shared.u64 t, %1; cvt.u32.u64 %0, t; }" : "=r"(a) : "l"(p));
    return a;
}
__device__ __forceinline__ void cp16(uint32_t dst, const void* src) {
    asm volatile("cp.async.cg.shared.global [%0], [%1], 16;" :: "r"(dst), "l"(src) : "memory");
}
__device__ __forceinline__ uint32_t pk2(float a, float b) {
    __nv_bfloat162 t = __floats2bfloat162_rn(a, b);
    return *reinterpret_cast<uint32_t*>(&t);
}
__device__ __forceinline__ void split4(const float4 v, uint2& hi, uint2& lo) {
    __nv_bfloat16 h0 = __float2bfloat16(v.x), h1 = __float2bfloat16(v.y);
    __nv_bfloat16 h2 = __float2bfloat16(v.z), h3 = __float2bfloat16(v.w);
    hi.x = pk2(v.x, v.y); hi.y = pk2(v.z, v.w);
    lo.x = pk2(v.x - __bfloat162float(h0), v.y - __bfloat162float(h1));
    lo.y = pk2(v.z - __bfloat162float(h2), v.w - __bfloat162float(h3));
}
__device__ __forceinline__ void ldm_x4(uint32_t* r, uint32_t addr) {
    asm volatile("ldmatrix.sync.aligned.m8n8.x4.shared.b16 {%0,%1,%2,%3}, [%4];"
                 : "=r"(r[0]), "=r"(r[1]), "=r"(r[2]), "=r"(r[3]) : "r"(addr));
}
__device__ __forceinline__ void ldm_x2(uint32_t* r, uint32_t addr) {
    asm volatile("ldmatrix.sync.aligned.m8n8.x2.shared.b16 {%0,%1}, [%2];"
                 : "=r"(r[0]), "=r"(r[1]) : "r"(addr));
}
__device__ __forceinline__ void mma16816(float* c, const uint32_t* a, const uint32_t* b) {
    asm volatile(
        "mma.sync.aligned.m16n8k16.row.col.f32.bf16.bf16.f32 "
        "{%0,%1,%2,%3}, {%4,%5,%6,%7}, {%8,%9}, {%0,%1,%2,%3};"
        : "+f"(c[0]), "+f"(c[1]), "+f"(c[2]), "+f"(c[3])
        : "r"(a[0]), "r"(a[1]), "r"(a[2]), "r"(a[3]), "r"(b[0]), "r"(b[1]));
}

// ---------------- LayerNorm -> bf16 hi/lo split --------------------------------
__global__ __launch_bounds__(256)
void ln_split_kernel(const float* __restrict__ x, const float* __restrict__ gamma,
                     const float* __restrict__ beta,
                     __nv_bfloat16* __restrict__ ohi, __nv_bfloat16* __restrict__ olo)
{
    const int row = blockIdx.x;
    const float4* xr = reinterpret_cast<const float4*>(x + (size_t)row * Cn);
    float4 v = xr[threadIdx.x];
    float s  = v.x + v.y + v.z + v.w;
    float ss = v.x*v.x + v.y*v.y + v.z*v.z + v.w*v.w;
    #pragma unroll
    for (int o = 16; o > 0; o >>= 1) {
        s  += __shfl_xor_sync(0xffffffffu, s,  o);
        ss += __shfl_xor_sync(0xffffffffu, ss, o);
    }
    __shared__ float rs[8], rss[8];
    const int w = threadIdx.x >> 5;
    if ((threadIdx.x & 31) == 0) { rs[w] = s; rss[w] = ss; }
    __syncthreads();
    if (threadIdx.x < 32) {
        float ts  = (threadIdx.x < 8) ? rs[threadIdx.x]  : 0.f;
        float tss = (threadIdx.x < 8) ? rss[threadIdx.x] : 0.f;
        #pragma unroll
        for (int o = 4; o > 0; o >>= 1) {
            ts  += __shfl_xor_sync(0xffffffffu, ts,  o);
            tss += __shfl_xor_sync(0xffffffffu, tss, o);
        }
        if (threadIdx.x == 0) {
            float mean = ts * (1.0f/Cn);
            float var  = tss * (1.0f/Cn) - mean*mean;
            rs[0]  = mean;
            rss[0] = rsqrtf(var + 1e-5f);
        }
    }
    __syncthreads();
    const float mean = rs[0], rstd = rss[0];
    const float4 g4 = reinterpret_cast<const float4*>(gamma)[threadIdx.x];
    const float4 b4 = reinterpret_cast<const float4*>(beta )[threadIdx.x];
    float4 o4;
    o4.x = (v.x - mean)*rstd*g4.x + b4.x;
    o4.y = (v.y - mean)*rstd*g4.y + b4.y;
    o4.z = (v.z - mean)*rstd*g4.z + b4.z;
    o4.w = (v.w - mean)*rstd*g4.w + b4.w;
    uint2 hi, lo; split4(o4, hi, lo);
    const size_t e = (size_t)row*Cn + threadIdx.x*4;
    *reinterpret_cast<uint2*>(ohi + e) = hi;
    *reinterpret_cast<uint2*>(olo + e) = lo;
}

// ---------------- weight transpose + split: W[K,N] -> Wt[N,K] hi/lo ------------
__global__ __launch_bounds__(256)
void wt_split_kernel(const float* __restrict__ W,
                     __nv_bfloat16* __restrict__ whi, __nv_bfloat16* __restrict__ wlo,
                     int K, int N)
{
    __shared__ float tile[32][33];
    const int n0 = blockIdx.x * 32, k0 = blockIdx.y * 32;
    const int tx = threadIdx.x & 31, ty = threadIdx.x >> 5;   // 32 x 8
    #pragma unroll
    for (int yy = ty; yy < 32; yy += 8)
        tile[yy][tx] = W[(size_t)(k0 + yy)*N + n0 + tx];
    __syncthreads();
    #pragma unroll
    for (int yy = ty; yy < 32; yy += 8) {
        const float v = tile[tx][yy];
        const __nv_bfloat16 h = __float2bfloat16(v);
        const __nv_bfloat16 l = __float2bfloat16(v - __bfloat162float(h));
        const size_t o = (size_t)(n0 + yy)*K + k0 + tx;
        whi[o] = h;
        wlo[o] = l;
    }
}

// ---------------- mma.sync bf16x3 GEMM (static smem <= 48KB) -------------------
// C = A @ B^T : A = Ahi+Alo [M,K] row-major, B rows = Wt[N,K] (hi/lo).
// Block 128x128, BK=16, 8 warps (2x4), warp tile 64x32, double-buffered cp.async.
// MODE 0: outF = C+bias ; MODE 1: outF = C+bias+resid ; MODE 2: relu(C+bias)->hi/lo
#define APITCH 48                      // bytes per row (16 bf16 = 32B + 16B pad)
#define TILE_B (128*APITCH)            // 6144 B
#define STG_B  (4*TILE_B)              // Ahi|Alo|Bhi|Blo = 24576 B
                                       // 2 stages = 49152 B static (48KB limit)

template<int MODE>
__global__ __launch_bounds__(256)
void tc_gemm(const __nv_bfloat16* __restrict__ Ahi, const __nv_bfloat16* __restrict__ Alo,
             const __nv_bfloat16* __restrict__ Bhi, const __nv_bfloat16* __restrict__ Blo,
             const float* __restrict__ bias, const float* __restrict__ resid,
             float* __restrict__ outF,
             __nv_bfloat16* __restrict__ outHi, __nv_bfloat16* __restrict__ outLo,
             int M, int N, int K)
{
    __shared__ __align__(16) char smem[2*STG_B];
    const uint32_t tb = smem_u32(smem);
    const int tid = threadIdx.x;
    const int wid = tid >> 5, lane = tid & 31;
    const int bm = blockIdx.y << 7, bn = blockIdx.x << 7;
    const int wm = (wid >> 2) * 64;      // warp M offset (0/64)
    const int wn = (wid & 3) * 32;       // warp N offset (0/32/64/96)

    float acc[4][4][4];
    #pragma unroll
    for (int i = 0; i < 4; ++i)
        #pragma unroll
        for (int j = 0; j < 4; ++j)
            #pragma unroll
            for (int q = 0; q < 4; ++q) acc[i][j][q] = 0.f;

    // per-stage loads: each tile = 128 rows x 32B = 256 16B-units; 1 unit/thread/tile
    const int lrow = tid >> 1, lc16 = tid & 1;
    const uint32_t lso = (uint32_t)(lrow*APITCH + lc16*16);

    auto issue_loads = [&](int c, int s) {
        const uint32_t st = tb + s*STG_B;
        const int kc = c << 4;
        const size_t ka = (size_t)(bm + lrow)*K + kc + lc16*8;
        const size_t kb = (size_t)(bn + lrow)*K + kc + lc16*8;
        cp16(st +            lso, Ahi + ka);
        cp16(st + TILE_B   + lso, Alo + ka);
        cp16(st + 2*TILE_B + lso, Bhi + kb);
        cp16(st + 3*TILE_B + lso, Blo + kb);
        asm volatile("cp.async.commit_group;" ::: "memory");
    };

    const int NK = K >> 4;
    issue_loads(0, 0);
    issue_loads(1, 1);

    // per-lane ldmatrix address components (16B aligned: APITCH % 16 == 0)
    const uint32_t a_r = (uint32_t)(wm + (lane & 15)) * APITCH + (lane >> 4) * 16;
    const uint32_t b_r = (uint32_t)(wn + (lane & 7)) * APITCH + ((lane >> 3) & 1) * 16;

    for (int c = 0; c < NK; ++c) {
        const int s = c & 1;
        if (c + 1 < NK) asm volatile("cp.async.wait_group 1;" ::: "memory");
        else            asm volatile("cp.async.wait_group 0;" ::: "memory");
        __syncthreads();
        const uint32_t st = tb + s*STG_B;

        uint32_t a[4][4], b_hi[4][2], b_lo[4][2];
        #pragma unroll
        for (int nf = 0; nf < 4; ++nf) {
            ldm_x2(b_hi[nf], st + 2*TILE_B + b_r + nf*8*APITCH);
            ldm_x2(b_lo[nf], st + 3*TILE_B + b_r + nf*8*APITCH);
        }
        // terms 1+2: Ahi*Bhi, Ahi*Blo
        #pragma unroll
        for (int mf = 0; mf < 4; ++mf)
            ldm_x4(a[mf], st + a_r + mf*16*APITCH);
        #pragma unroll
        for (int mf = 0; mf < 4; ++mf)
            #pragma unroll
            for (int nf = 0; nf < 4; ++nf) {
                mma16816(acc[mf][nf], a[mf], b_hi[nf]);
                mma16816(acc[mf][nf], a[mf], b_lo[nf]);
            }
        // term 3: Alo*Bhi
        #pragma unroll
        for (int mf = 0; mf < 4; ++mf)
            ldm_x4(a[mf], st + TILE_B + a_r + mf*16*APITCH);
        #pragma unroll
        for (int mf = 0; mf < 4; ++mf)
            #pragma unroll
            for (int nf = 0; nf < 4; ++nf)
                mma16816(acc[mf][nf], a[mf], b_hi[nf]);

        __syncthreads();
        if (c + 2 < NK) issue_loads(c + 2, s);
    }

    // -------- epilogue: fragments direct to global ----------------------------
    const int qr = lane >> 2, qc = (lane & 3) * 2;
    #pragma unroll
    for (int mf = 0; mf < 4; ++mf) {
        #pragma unroll
        for (int half = 0; half < 2; ++half) {
            const int r = bm + wm + mf*16 + qr + half*8;
            #pragma unroll
            for (int nf = 0; nf < 4; ++nf) {
                const int n = bn + wn + nf*8 + qc;
                float c0 = acc[mf][nf][half*2+0] + bias[n];
                float c1 = acc[mf][nf][half*2+1] + bias[n+1];
                const size_t go = (size_t)r*N + n;
                if (MODE == 1) {
                    const float2 rr = *reinterpret_cast<const float2*>(&resid[go]);
                    c0 += rr.x; c1 += rr.y;
                }
                if (MODE == 2) {
                    c0 = fmaxf(c0, 0.f); c1 = fmaxf(c1, 0.f);
                    const __nv_bfloat16 h0 = __float2bfloat16(c0);
                    const __nv_bfloat16 h1 = __float2bfloat16(c1);
                    *reinterpret_cast<uint32_t*>(outHi + go) = pk2(c0, c1);
                    *reinterpret_cast<uint32_t*>(outLo + go) =
                        pk2(c0 - __bfloat162float(h0), c1 - __bfloat162float(h1));
                } else {
                    float2 o; o.x = c0; o.y = c1;
                    *reinterpret_cast<float2*>(&outF[go]) = o;
                }
            }
        }
    }
}

// ---------------- Flash attention (fp32, epilogue splits y to hi/lo) -----------
__global__ __launch_bounds__(256)
void attn_kernel(const float* __restrict__ qkv, const int* __restrict__ seq_ls,
                 __nv_bfloat16* __restrict__ yhi, __nv_bfloat16* __restrict__ ylo)
{
    const int qt = blockIdx.x, h = blockIdx.y, b = blockIdx.z;

    __shared__ float Qs[64][68];
    __shared__ float Ks[32][68];
    __shared__ float Vs[32][68];
    __shared__ float Ss[64][33];
    __shared__ float m_s[64], l_s[64], fac[64];

    const int tid = threadIdx.x;
    const int ty = tid >> 4, tx = tid & 15;
    const int seq_l = seq_ls[b];

    for (int i = tid; i < 64*16; i += 256) {
        const int r = i >> 4, cq = (i & 15) << 2;
        const int bt = b*Tn + qt*64 + r;
        float4 v = *reinterpret_cast<const float4*>(&qkv[(size_t)bt*3*Cn + h*HDd + cq]);
        v.x *= 0.125f; v.y *= 0.125f; v.z *= 0.125f; v.w *= 0.125f;
        *reinterpret_cast<float4*>(&Qs[r][cq]) = v;
    }
    if (tid < 64) { m_s[tid] = -3.0e38f; l_s[tid] = 0.f; }

    float acc[4][4];
    #pragma unroll
    for (int i = 0; i < 4; ++i)
        #pragma unroll
        for (int j = 0; j < 4; ++j) acc[i][j] = 0.f;

    const int r0 = ty*4;
    const int nkt = (seq_l + 31) >> 5;
    __syncthreads();

    for (int kb = 0; kb < nkt; ++kb) {
        const int kbase = kb << 5;
        for (int i = tid; i < 32*16; i += 256) {
            const int r = i >> 4, cq = (i & 15) << 2;
            const int bt = b*Tn + kbase + r;
            *reinterpret_cast<float4*>(&Ks[r][cq]) =
                *reinterpret_cast<const float4*>(&qkv[(size_t)bt*3*Cn + Cn   + h*HDd + cq]);
            *reinterpret_cast<float4*>(&Vs[r][cq]) =
                *reinterpret_cast<const float4*>(&qkv[(size_t)bt*3*Cn + 2*Cn + h*HDd + cq]);
        }
        __syncthreads();

        #pragma unroll
        for (int j = 0; j < 2; ++j) {
            const int c = (tx << 1) + j;
            float s0 = 0.f, s1 = 0.f, s2 = 0.f, s3 = 0.f;
            #pragma unroll
            for (int d4 = 0; d4 < 16; ++d4) {
                const float4 kv = *reinterpret_cast<const float4*>(&Ks[c][d4*4]);
                const float4 q0 = *reinterpret_cast<const float4*>(&Qs[r0+0][d4*4]);
                const float4 q1 = *reinterpret_cast<const float4*>(&Qs[r0+1][d4*4]);
                const float4 q2 = *reinterpret_cast<const float4*>(&Qs[r0+2][d4*4]);
                const float4 q3 = *reinterpret_cast<const float4*>(&Qs[r0+3][d4*4]);
                s0 += q0.x*kv.x + q0.y*kv.y + q0.z*kv.z + q0.w*kv.w;
                s1 += q1.x*kv.x + q1.y*kv.y + q1.z*kv.z + q1.w*kv.w;
                s2 += q2.x*kv.x + q2.y*kv.y + q2.z*kv.z + q2.w*kv.w;
                s3 += q3.x*kv.x + q3.y*kv.y + q3.z*kv.z + q3.w*kv.w;
            }
            const bool valid = (kbase + c) < seq_l;
            Ss[r0+0][c] = valid ? s0 : -1.0e30f;
            Ss[r0+1][c] = valid ? s1 : -1.0e30f;
            Ss[r0+2][c] = valid ? s2 : -1.0e30f;
            Ss[r0+3][c] = valid ? s3 : -1.0e30f;
        }
        __syncthreads();

        if (tid < 64) {
            const float m_old = m_s[tid];
            float mx = m_old;
            #pragma unroll
            for (int c = 0; c < 32; ++c) mx = fmaxf(mx, Ss[tid][c]);
            const float f = __expf(m_old - mx);
            float sum = 0.f;
            #pragma unroll
            for (int c = 0; c < 32; ++c) {
                const float p = __expf(Ss[tid][c] - mx);
                Ss[tid][c] = p;
                sum += p;
            }
            m_s[tid] = mx;
            l_s[tid] = l_s[tid] * f + sum;
            fac[tid] = f;
        }
        __syncthreads();

        const float f0 = fac[r0+0], f1 = fac[r0+1], f2 = fac[r0+2], f3 = fac[r0+3];
        #pragma unroll
        for (int j = 0; j < 4; ++j) {
            acc[0][j] *= f0; acc[1][j] *= f1; acc[2][j] *= f2; acc[3][j] *= f3;
        }
        #pragma unroll
        for (int k = 0; k < 32; ++k) {
            const float4 v4 = *reinterpret_cast<const float4*>(&Vs[k][tx*4]);
            const float p0 = Ss[r0+0][k], p1 = Ss[r0+1][k];
            const float p2 = Ss[r0+2][k], p3 = Ss[r0+3][k];
            acc[0][0] += p0*v4.x; acc[0][1] += p0*v4.y; acc[0][2] += p0*v4.z; acc[0][3] += p0*v4.w;
            acc[1][0] += p1*v4.x; acc[1][1] += p1*v4.y; acc[1][2] += p1*v4.z; acc[1][3] += p1*v4.w;
            acc[2][0] += p2*v4.x; acc[2][1] += p2*v4.y; acc[2][2] += p2*v4.z; acc[2][3] += p2*v4.w;
            acc[3][0] += p3*v4.x; acc[3][1] += p3*v4.y; acc[3][2] += p3*v4.z; acc[3][3] += p3*v4.w;
        }
        __syncthreads();
    }

    #pragma unroll
    for (int i = 0; i < 4; ++i) {
        const int r = r0 + i;
        const float inv = 1.0f / l_s[r];
        const int bt = b*Tn + qt*64 + r;
        float4 o;
        o.x = acc[i][0]*inv; o.y = acc[i][1]*inv;
        o.z = acc[i][2]*inv; o.w = acc[i][3]*inv;
        uint2 hi, lo; split4(o, hi, lo);
        const size_t e = (size_t)bt*Cn + h*HDd + tx*4;
        *reinterpret_cast<uint2*>(yhi + e) = hi;
        *reinterpret_cast<uint2*>(ylo + e) = lo;
    }
}

// ---------------- launch ------------------------------------------------------
extern "C" void kernel_launch(void* const* d_in, const int* in_sizes, int n_in,
                              void* d_out, int out_size)
{
    const float* x      = (const float*)d_in[0];
    const int*   seq_ls = (const int*)  d_in[1];
    const float* ln1_g  = (const float*)d_in[2];
    const float* ln1_b  = (const float*)d_in[3];
    const float* w_qkv  = (const float*)d_in[4];
    const float* b_qkv  = (const float*)d_in[5];
    const float* w_proj = (const float*)d_in[6];
    const float* b_proj = (const float*)d_in[7];
    const float* ln2_g  = (const float*)d_in[8];
    const float* ln2_b  = (const float*)d_in[9];
    const float* w_fc   = (const float*)d_in[10];
    const float* b_fc   = (const float*)d_in[11];
    const float* w_fc2  = (const float*)d_in[12];
    const float* b_fc2  = (const float*)d_in[13];
    float* out = (float*)d_out;

    float *qkv, *x1;
    __nv_bfloat16 *ahi, *alo, *yhi, *ylo, *ffhi, *fflo, *whi, *wlo;
    cudaGetSymbolAddress((void**)&qkv,  g_qkv);
    cudaGetSymbolAddress((void**)&x1,   g_x1);
    cudaGetSymbolAddress((void**)&ahi,  g_ahi);
    cudaGetSymbolAddress((void**)&alo,  g_alo);
    cudaGetSymbolAddress((void**)&yhi,  g_yhi);
    cudaGetSymbolAddress((void**)&ylo,  g_ylo);
    cudaGetSymbolAddress((void**)&ffhi, g_ffhi);
    cudaGetSymbolAddress((void**)&fflo, g_fflo);
    cudaGetSymbolAddress((void**)&whi,  g_whi);
    cudaGetSymbolAddress((void**)&wlo,  g_wlo);

    // 0. transpose+split weights -> [N,K] bf16 hi/lo
    wt_split_kernel<<<dim3(3*Cn/32, Cn/32), 256>>>(w_qkv,  whi+OFF_QKV,  wlo+OFF_QKV,  Cn,  3*Cn);
    wt_split_kernel<<<dim3(Cn/32,   Cn/32), 256>>>(w_proj, whi+OFF_PROJ, wlo+OFF_PROJ, Cn,  Cn);
    wt_split_kernel<<<dim3(FFf/32,  Cn/32), 256>>>(w_fc,   whi+OFF_FC,   wlo+OFF_FC,   Cn,  FFf);
    wt_split_kernel<<<dim3(Cn/32,  FFf/32), 256>>>(w_fc2,  whi+OFF_FC2,  wlo+OFF_FC2,  FFf, Cn);

    // 1. LN1 -> hi/lo
    ln_split_kernel<<<MROWS, 256>>>(x, ln1_g, ln1_b, ahi, alo);
    // 2. QKV projection (fp32 out for attention)
    tc_gemm<0><<<dim3(3*Cn/128, MROWS/128), 256>>>(
        ahi, alo, whi+OFF_QKV, wlo+OFF_QKV, b_qkv, nullptr, qkv, nullptr, nullptr,
        MROWS, 3*Cn, Cn);
    // 3. Attention -> y hi/lo
    attn_kernel<<<dim3(Tn/64, NHh, Bn), 256>>>(qkv, seq_ls, yhi, ylo);
    // 4. proj + residual(x) -> x1 (fp32)
    tc_gemm<1><<<dim3(Cn/128, MROWS/128), 256>>>(
        yhi, ylo, whi+OFF_PROJ, wlo+OFF_PROJ, b_proj, x, x1, nullptr, nullptr,
        MROWS, Cn, Cn);
    // 5. LN2 -> hi/lo
    ln_split_kernel<<<MROWS, 256>>>(x1, ln2_g, ln2_b, ahi, alo);
    // 6. FC + ReLU -> ff hi/lo
    tc_gemm<2><<<dim3(FFf/128, MROWS/128), 256>>>(
        ahi, alo, whi+OFF_FC, wlo+OFF_FC, b_fc, nullptr, nullptr, ffhi, fflo,
        MROWS, FFf, Cn);
    // 7. FC2 + residual(x1) -> out
    tc_gemm<1><<<dim3(Cn/128, MROWS/128), 256>>>(
        ffhi, fflo, whi+OFF_FC2, wlo+OFF_FC2, b_fc2, x1, out, nullptr, nullptr,
        MROWS, Cn, FFf);
}

// round 8
// speedup vs baseline: 2.5307x; 1.6081x over previous
#include <cuda_runtime.h>
#include <cuda_fp16.h>
#include <cstdint>
#include <math.h>

// Problem dims (fixed)
#define Bn 8
#define Tn 1024
#define Cn 1024
#define NHh 16
#define HDd 64
#define FFf 4096
#define MROWS (Bn*Tn)   // 8192

// Weight offsets inside the packed transposed-weight buffer (elements)
#define OFF_QKV 0
#define OFF_PROJ (3*Cn*Cn)
#define OFF_FC   (OFF_PROJ + Cn*Cn)
#define OFF_FC2  (OFF_FC + (size_t)FFf*Cn)
#define WSUM     (OFF_FC2 + (size_t)Cn*FFf)

// ---------------- scratch (static device globals; no allocation) -------------
static __device__ __align__(16) float   g_qkv[(size_t)MROWS*3*Cn];  // 96 MB
static __device__ __align__(16) float   g_x1 [(size_t)MROWS*Cn];    // 32 MB
static __device__ __align__(16) __half  g_ah [(size_t)MROWS*Cn];    // LN out fp16
static __device__ __align__(16) __half  g_yh [(size_t)MROWS*Cn];    // attn out fp16
static __device__ __align__(16) __half  g_ffh[(size_t)MROWS*FFf];   // relu(fc) fp16
static __device__ __align__(16) __half  g_wh [WSUM];                // W^T fp16

// ---------------- small helpers ------------------------------------------------
__device__ __forceinline__ uint32_t smem_u32(const void* p) {
    uint32_t a;
    asm("{ .reg .u64 t; cvta.to.shared.u64 t, %1; cvt.u32.u64 %0, t; }" : "=r"(a) : "l"(p));
    return a;
}
__device__ __forceinline__ void cp16(uint32_t dst, const void* src) {
    asm volatile("cp.async.cg.shared.global [%0], [%1], 16;" :: "r"(dst), "l"(src) : "memory");
}
__device__ __forceinline__ uint32_t pkh2(float a, float b) {
    __half2 t = __floats2half2_rn(a, b);
    return *reinterpret_cast<uint32_t*>(&t);
}
__device__ __forceinline__ void ldm_x4(uint32_t* r, uint32_t addr) {
    asm volatile("ldmatrix.sync.aligned.m8n8.x4.shared.b16 {%0,%1,%2,%3}, [%4];"
                 : "=r"(r[0]), "=r"(r[1]), "=r"(r[2]), "=r"(r[3]) : "r"(addr));
}
__device__ __forceinline__ void ldm_x2(uint32_t* r, uint32_t addr) {
    asm volatile("ldmatrix.sync.aligned.m8n8.x2.shared.b16 {%0,%1}, [%2];"
                 : "=r"(r[0]), "=r"(r[1]) : "r"(addr));
}
__device__ __forceinline__ void mma16816(float* c, const uint32_t* a, const uint32_t* b) {
    asm volatile(
        "mma.sync.aligned.m16n8k16.row.col.f32.f16.f16.f32 "
        "{%0,%1,%2,%3}, {%4,%5,%6,%7}, {%8,%9}, {%0,%1,%2,%3};"
        : "+f"(c[0]), "+f"(c[1]), "+f"(c[2]), "+f"(c[3])
        : "r"(a[0]), "r"(a[1]), "r"(a[2]), "r"(a[3]), "r"(b[0]), "r"(b[1]));
}

// ---------------- LayerNorm -> fp16 --------------------------------------------
__global__ __launch_bounds__(256)
void ln_h_kernel(const float* __restrict__ x, const float* __restrict__ gamma,
                 const float* __restrict__ beta, __half* __restrict__ oh)
{
    const int row = blockIdx.x;
    const float4* xr = reinterpret_cast<const float4*>(x + (size_t)row * Cn);
    float4 v = xr[threadIdx.x];
    float s  = v.x + v.y + v.z + v.w;
    float ss = v.x*v.x + v.y*v.y + v.z*v.z + v.w*v.w;
    #pragma unroll
    for (int o = 16; o > 0; o >>= 1) {
        s  += __shfl_xor_sync(0xffffffffu, s,  o);
        ss += __shfl_xor_sync(0xffffffffu, ss, o);
    }
    __shared__ float rs[8], rss[8];
    const int w = threadIdx.x >> 5;
    if ((threadIdx.x & 31) == 0) { rs[w] = s; rss[w] = ss; }
    __syncthreads();
    if (threadIdx.x < 32) {
        float ts  = (threadIdx.x < 8) ? rs[threadIdx.x]  : 0.f;
        float tss = (threadIdx.x < 8) ? rss[threadIdx.x] : 0.f;
        #pragma unroll
        for (int o = 4; o > 0; o >>= 1) {
            ts  += __shfl_xor_sync(0xffffffffu, ts,  o);
            tss += __shfl_xor_sync(0xffffffffu, tss, o);
        }
        if (threadIdx.x == 0) {
            float mean = ts * (1.0f/Cn);
            float var  = tss * (1.0f/Cn) - mean*mean;
            rs[0]  = mean;
            rss[0] = rsqrtf(var + 1e-5f);
        }
    }
    __syncthreads();
    const float mean = rs[0], rstd = rss[0];
    const float4 g4 = reinterpret_cast<const float4*>(gamma)[threadIdx.x];
    const float4 b4 = reinterpret_cast<const float4*>(beta )[threadIdx.x];
    uint2 h;
    h.x = pkh2((v.x - mean)*rstd*g4.x + b4.x, (v.y - mean)*rstd*g4.y + b4.y);
    h.y = pkh2((v.z - mean)*rstd*g4.z + b4.z, (v.w - mean)*rstd*g4.w + b4.w);
    *reinterpret_cast<uint2*>(oh + (size_t)row*Cn + threadIdx.x*4) = h;
}

// ---------------- weight transpose: W[K,N] -> Wt[N,K] fp16 ---------------------
__global__ __launch_bounds__(256)
void wt_h_kernel(const float* __restrict__ W, __half* __restrict__ wh, int K, int N)
{
    __shared__ float tile[32][33];
    const int n0 = blockIdx.x * 32, k0 = blockIdx.y * 32;
    const int tx = threadIdx.x & 31, ty = threadIdx.x >> 5;   // 32 x 8
    #pragma unroll
    for (int yy = ty; yy < 32; yy += 8)
        tile[yy][tx] = W[(size_t)(k0 + yy)*N + n0 + tx];
    __syncthreads();
    #pragma unroll
    for (int yy = ty; yy < 32; yy += 8)
        wh[(size_t)(n0 + yy)*K + k0 + tx] = __float2half_rn(tile[tx][yy]);
}

// ---------------- mma.sync fp16 GEMM (static smem 40KB) ------------------------
// C = A @ B^T : A [M,K] fp16 row-major, B rows = Wt[N,K] fp16.
// Block 128x128, BK=32, 8 warps (2x4), warp tile 64x32, double-buffered cp.async.
// MODE 0: outF = C+bias ; MODE 1: outF = C+bias+resid ; MODE 2: relu(C+bias)->fp16
#define APITCH 80                      // bytes per row (32 fp16 = 64B + 16B pad)
#define TILE_B (128*APITCH)            // 10240 B
#define STG_B  (2*TILE_B)              // A|B = 20480 B ; 2 stages = 40960 B

template<int MODE>
__global__ __launch_bounds__(256)
void tc_gemm(const __half* __restrict__ Ah, const __half* __restrict__ Bh,
             const float* __restrict__ bias, const float* __restrict__ resid,
             float* __restrict__ outF, __half* __restrict__ outH,
             int M, int N, int K)
{
    __shared__ __align__(16) char smem[2*STG_B];
    const uint32_t tb = smem_u32(smem);
    const int tid = threadIdx.x;
    const int wid = tid >> 5, lane = tid & 31;
    const int bm = blockIdx.y << 7, bn = blockIdx.x << 7;
    const int wm = (wid >> 2) * 64;      // warp M offset (0/64)
    const int wn = (wid & 3) * 32;       // warp N offset (0/32/64/96)

    float acc[4][4][4];
    #pragma unroll
    for (int i = 0; i < 4; ++i)
        #pragma unroll
        for (int j = 0; j < 4; ++j)
            #pragma unroll
            for (int q = 0; q < 4; ++q) acc[i][j][q] = 0.f;

    // loads: per tile 128 rows x 4 chunks(16B) = 512 units; 256 thr x 2
    auto issue_loads = [&](int c, int s) {
        const uint32_t st = tb + s*STG_B;
        const int kc = c << 5;
        #pragma unroll
        for (int i = 0; i < 2; ++i) {
            const int u = tid + i*256;
            const int row = u >> 2, ch = u & 3;
            const uint32_t so = (uint32_t)(row*APITCH + ch*16);
            cp16(st +          so, Ah + (size_t)(bm + row)*K + kc + ch*8);
            cp16(st + TILE_B + so, Bh + (size_t)(bn + row)*K + kc + ch*8);
        }
        asm volatile("cp.async.commit_group;" ::: "memory");
    };

    const int NK = K >> 5;
    issue_loads(0, 0);
    issue_loads(1, 1);

    // per-lane ldmatrix address components
    const uint32_t a_r = (uint32_t)(wm + (lane & 15)) * APITCH + (lane >> 4) * 16;
    const uint32_t b_r = (uint32_t)(wn + (lane & 7)) * APITCH + ((lane >> 3) & 1) * 16;

    for (int c = 0; c < NK; ++c) {
        const int s = c & 1;
        if (c + 1 < NK) asm volatile("cp.async.wait_group 1;" ::: "memory");
        else            asm volatile("cp.async.wait_group 0;" ::: "memory");
        __syncthreads();
        const uint32_t st = tb + s*STG_B;

        #pragma unroll
        for (int ks = 0; ks < 2; ++ks) {
            const uint32_t ko = ks * 32;           // 16 fp16 = 32 bytes
            uint32_t a[4][4], b[4][2];
            #pragma unroll
            for (int nf = 0; nf < 4; ++nf)
                ldm_x2(b[nf], st + TILE_B + b_r + ko + nf*8*APITCH);
            #pragma unroll
            for (int mf = 0; mf < 4; ++mf)
                ldm_x4(a[mf], st + a_r + ko + mf*16*APITCH);
            #pragma unroll
            for (int mf = 0; mf < 4; ++mf)
                #pragma unroll
                for (int nf = 0; nf < 4; ++nf)
                    mma16816(acc[mf][nf], a[mf], b[nf]);
        }
        __syncthreads();
        if (c + 2 < NK) issue_loads(c + 2, s);
    }

    // -------- epilogue: fragments direct to global ----------------------------
    const int qr = lane >> 2, qc = (lane & 3) * 2;
    #pragma unroll
    for (int mf = 0; mf < 4; ++mf) {
        #pragma unroll
        for (int half_ = 0; half_ < 2; ++half_) {
            const int r = bm + wm + mf*16 + qr + half_*8;
            #pragma unroll
            for (int nf = 0; nf < 4; ++nf) {
                const int n = bn + wn + nf*8 + qc;
                float c0 = acc[mf][nf][half_*2+0] + bias[n];
                float c1 = acc[mf][nf][half_*2+1] + bias[n+1];
                const size_t go = (size_t)r*N + n;
                if (MODE == 1) {
                    const float2 rr = *reinterpret_cast<const float2*>(&resid[go]);
                    c0 += rr.x; c1 += rr.y;
                }
                if (MODE == 2) {
                    c0 = fmaxf(c0, 0.f); c1 = fmaxf(c1, 0.f);
                    *reinterpret_cast<uint32_t*>(outH + go) = pkh2(c0, c1);
                } else {
                    float2 o; o.x = c0; o.y = c1;
                    *reinterpret_cast<float2*>(&outF[go]) = o;
                }
            }
        }
    }
}

// ---------------- Flash attention (fp32, epilogue -> fp16) ---------------------
__global__ __launch_bounds__(256)
void attn_kernel(const float* __restrict__ qkv, const int* __restrict__ seq_ls,
                 __half* __restrict__ yh)
{
    const int qt = blockIdx.x, h = blockIdx.y, b = blockIdx.z;

    __shared__ float Qs[64][68];
    __shared__ float Ks[32][68];
    __shared__ float Vs[32][68];
    __shared__ float Ss[64][33];
    __shared__ float m_s[64], l_s[64], fac[64];

    const int tid = threadIdx.x;
    const int ty = tid >> 4, tx = tid & 15;
    const int seq_l = seq_ls[b];

    for (int i = tid; i < 64*16; i += 256) {
        const int r = i >> 4, cq = (i & 15) << 2;
        const int bt = b*Tn + qt*64 + r;
        float4 v = *reinterpret_cast<const float4*>(&qkv[(size_t)bt*3*Cn + h*HDd + cq]);
        v.x *= 0.125f; v.y *= 0.125f; v.z *= 0.125f; v.w *= 0.125f;
        *reinterpret_cast<float4*>(&Qs[r][cq]) = v;
    }
    if (tid < 64) { m_s[tid] = -3.0e38f; l_s[tid] = 0.f; }

    float acc[4][4];
    #pragma unroll
    for (int i = 0; i < 4; ++i)
        #pragma unroll
        for (int j = 0; j < 4; ++j) acc[i][j] = 0.f;

    const int r0 = ty*4;
    const int nkt = (seq_l + 31) >> 5;
    __syncthreads();

    for (int kb = 0; kb < nkt; ++kb) {
        const int kbase = kb << 5;
        for (int i = tid; i < 32*16; i += 256) {
            const int r = i >> 4, cq = (i & 15) << 2;
            const int bt = b*Tn + kbase + r;
            *reinterpret_cast<float4*>(&Ks[r][cq]) =
                *reinterpret_cast<const float4*>(&qkv[(size_t)bt*3*Cn + Cn   + h*HDd + cq]);
            *reinterpret_cast<float4*>(&Vs[r][cq]) =
                *reinterpret_cast<const float4*>(&qkv[(size_t)bt*3*Cn + 2*Cn + h*HDd + cq]);
        }
        __syncthreads();

        #pragma unroll
        for (int j = 0; j < 2; ++j) {
            const int c = (tx << 1) + j;
            float s0 = 0.f, s1 = 0.f, s2 = 0.f, s3 = 0.f;
            #pragma unroll
            for (int d4 = 0; d4 < 16; ++d4) {
                const float4 kv = *reinterpret_cast<const float4*>(&Ks[c][d4*4]);
                const float4 q0 = *reinterpret_cast<const float4*>(&Qs[r0+0][d4*4]);
                const float4 q1 = *reinterpret_cast<const float4*>(&Qs[r0+1][d4*4]);
                const float4 q2 = *reinterpret_cast<const float4*>(&Qs[r0+2][d4*4]);
                const float4 q3 = *reinterpret_cast<const float4*>(&Qs[r0+3][d4*4]);
                s0 += q0.x*kv.x + q0.y*kv.y + q0.z*kv.z + q0.w*kv.w;
                s1 += q1.x*kv.x + q1.y*kv.y + q1.z*kv.z + q1.w*kv.w;
                s2 += q2.x*kv.x + q2.y*kv.y + q2.z*kv.z + q2.w*kv.w;
                s3 += q3.x*kv.x + q3.y*kv.y + q3.z*kv.z + q3.w*kv.w;
            }
            const bool valid = (kbase + c) < seq_l;
            Ss[r0+0][c] = valid ? s0 : -1.0e30f;
            Ss[r0+1][c] = valid ? s1 : -1.0e30f;
            Ss[r0+2][c] = valid ? s2 : -1.0e30f;
            Ss[r0+3][c] = valid ? s3 : -1.0e30f;
        }
        __syncthreads();

        if (tid < 64) {
            const float m_old = m_s[tid];
            float mx = m_old;
            #pragma unroll
            for (int c = 0; c < 32; ++c) mx = fmaxf(mx, Ss[tid][c]);
            const float f = __expf(m_old - mx);
            float sum = 0.f;
            #pragma unroll
            for (int c = 0; c < 32; ++c) {
                const float p = __expf(Ss[tid][c] - mx);
                Ss[tid][c] = p;
                sum += p;
            }
            m_s[tid] = mx;
            l_s[tid] = l_s[tid] * f + sum;
            fac[tid] = f;
        }
        __syncthreads();

        const float f0 = fac[r0+0], f1 = fac[r0+1], f2 = fac[r0+2], f3 = fac[r0+3];
        #pragma unroll
        for (int j = 0; j < 4; ++j) {
            acc[0][j] *= f0; acc[1][j] *= f1; acc[2][j] *= f2; acc[3][j] *= f3;
        }
        #pragma unroll
        for (int k = 0; k < 32; ++k) {
            const float4 v4 = *reinterpret_cast<const float4*>(&Vs[k][tx*4]);
            const float p0 = Ss[r0+0][k], p1 = Ss[r0+1][k];
            const float p2 = Ss[r0+2][k], p3 = Ss[r0+3][k];
            acc[0][0] += p0*v4.x; acc[0][1] += p0*v4.y; acc[0][2] += p0*v4.z; acc[0][3] += p0*v4.w;
            acc[1][0] += p1*v4.x; acc[1][1] += p1*v4.y; acc[1][2] += p1*v4.z; acc[1][3] += p1*v4.w;
            acc[2][0] += p2*v4.x; acc[2][1] += p2*v4.y; acc[2][2] += p2*v4.z; acc[2][3] += p2*v4.w;
            acc[3][0] += p3*v4.x; acc[3][1] += p3*v4.y; acc[3][2] += p3*v4.z; acc[3][3] += p3*v4.w;
        }
        __syncthreads();
    }

    #pragma unroll
    for (int i = 0; i < 4; ++i) {
        const int r = r0 + i;
        const float inv = 1.0f / l_s[r];
        const int bt = b*Tn + qt*64 + r;
        uint2 hh;
        hh.x = pkh2(acc[i][0]*inv, acc[i][1]*inv);
        hh.y = pkh2(acc[i][2]*inv, acc[i][3]*inv);
        *reinterpret_cast<uint2*>(yh + (size_t)bt*Cn + h*HDd + tx*4) = hh;
    }
}

// ---------------- launch ------------------------------------------------------
extern "C" void kernel_launch(void* const* d_in, const int* in_sizes, int n_in,
                              void* d_out, int out_size)
{
    const float* x      = (const float*)d_in[0];
    const int*   seq_ls = (const int*)  d_in[1];
    const float* ln1_g  = (const float*)d_in[2];
    const float* ln1_b  = (const float*)d_in[3];
    const float* w_qkv  = (const float*)d_in[4];
    const float* b_qkv  = (const float*)d_in[5];
    const float* w_proj = (const float*)d_in[6];
    const float* b_proj = (const float*)d_in[7];
    const float* ln2_g  = (const float*)d_in[8];
    const float* ln2_b  = (const float*)d_in[9];
    const float* w_fc   = (const float*)d_in[10];
    const float* b_fc   = (const float*)d_in[11];
    const float* w_fc2  = (const float*)d_in[12];
    const float* b_fc2  = (const float*)d_in[13];
    float* out = (float*)d_out;

    float *qkv, *x1;
    __half *ah, *yh, *ffh, *wh;
    cudaGetSymbolAddress((void**)&qkv, g_qkv);
    cudaGetSymbolAddress((void**)&x1,  g_x1);
    cudaGetSymbolAddress((void**)&ah,  g_ah);
    cudaGetSymbolAddress((void**)&yh,  g_yh);
    cudaGetSymbolAddress((void**)&ffh, g_ffh);
    cudaGetSymbolAddress((void**)&wh,  g_wh);

    // 0. transpose weights -> [N,K] fp16
    wt_h_kernel<<<dim3(3*Cn/32, Cn/32), 256>>>(w_qkv,  wh+OFF_QKV,  Cn,  3*Cn);
    wt_h_kernel<<<dim3(Cn/32,   Cn/32), 256>>>(w_proj, wh+OFF_PROJ, Cn,  Cn);
    wt_h_kernel<<<dim3(FFf/32,  Cn/32), 256>>>(w_fc,   wh+OFF_FC,   Cn,  FFf);
    wt_h_kernel<<<dim3(Cn/32,  FFf/32), 256>>>(w_fc2,  wh+OFF_FC2,  FFf, Cn);

    // 1. LN1 -> fp16
    ln_h_kernel<<<MROWS, 256>>>(x, ln1_g, ln1_b, ah);
    // 2. QKV projection (fp32 out for attention)
    tc_gemm<0><<<dim3(3*Cn/128, MROWS/128), 256>>>(
        ah, wh+OFF_QKV, b_qkv, nullptr, qkv, nullptr, MROWS, 3*Cn, Cn);
    // 3. Attention -> y fp16
    attn_kernel<<<dim3(Tn/64, NHh, Bn), 256>>>(qkv, seq_ls, yh);
    // 4. proj + residual(x) -> x1 (fp32)
    tc_gemm<1><<<dim3(Cn/128, MROWS/128), 256>>>(
        yh, wh+OFF_PROJ, b_proj, x, x1, nullptr, MROWS, Cn, Cn);
    // 5. LN2 -> fp16
    ln_h_kernel<<<MROWS, 256>>>(x1, ln2_g, ln2_b, ah);
    // 6. FC + ReLU -> ff fp16
    tc_gemm<2><<<dim3(FFf/128, MROWS/128), 256>>>(
        ah, wh+OFF_FC, b_fc, nullptr, nullptr, ffh, MROWS, FFf, Cn);
    // 7. FC2 + residual(x1) -> out
    tc_gemm<1><<<dim3(Cn/128, MROWS/128), 256>>>(
        ffh, wh+OFF_FC2, b_fc2, x1, out, nullptr, MROWS, Cn, FFf);
}

// round 11
// speedup vs baseline: 5.1140x; 2.0208x over previous
#include <cuda_runtime.h>
#include <cuda_fp16.h>
#include <cstdint>
#include <math.h>

// Problem dims (fixed)
#define Bn 8
#define Tn 1024
#define Cn 1024
#define NHh 16
#define HDd 64
#define FFf 4096
#define MROWS (Bn*Tn)   // 8192

// Weight offsets inside the packed transposed-weight buffer (elements)
#define OFF_QKV 0
#define OFF_PROJ (3*Cn*Cn)
#define OFF_FC   (OFF_PROJ + Cn*Cn)
#define OFF_FC2  (OFF_FC + (size_t)FFf*Cn)
#define WSUM     (OFF_FC2 + (size_t)Cn*FFf)

// ---------------- scratch (static device globals; no allocation) -------------
static __device__ __align__(16) float   g_qkv[(size_t)MROWS*3*Cn];  // 96 MB
static __device__ __align__(16) float   g_x1 [(size_t)MROWS*Cn];    // 32 MB
static __device__ __align__(16) __half  g_ah [(size_t)MROWS*Cn];    // LN out fp16
static __device__ __align__(16) __half  g_yh [(size_t)MROWS*Cn];    // attn out fp16
static __device__ __align__(16) __half  g_ffh[(size_t)MROWS*FFf];   // relu(fc) fp16
static __device__ __align__(16) __half  g_wh [WSUM];                // W^T fp16

// ---------------- small helpers ------------------------------------------------
__device__ __forceinline__ uint32_t smem_u32(const void* p) {
    uint32_t a;
    asm("{ .reg .u64 t; cvta.to.shared.u64 t, %1; cvt.u32.u64 %0, t; }" : "=r"(a) : "l"(p));
    return a;
}
__device__ __forceinline__ void cp16(uint32_t dst, const void* src) {
    asm volatile("cp.async.cg.shared.global [%0], [%1], 16;" :: "r"(dst), "l"(src) : "memory");
}
__device__ __forceinline__ uint32_t pkh2(float a, float b) {
    __half2 t = __floats2half2_rn(a, b);
    return *reinterpret_cast<uint32_t*>(&t);
}
__device__ __forceinline__ void ldm_x4(uint32_t* r, uint32_t addr) {
    asm volatile("ldmatrix.sync.aligned.m8n8.x4.shared.b16 {%0,%1,%2,%3}, [%4];"
                 : "=r"(r[0]), "=r"(r[1]), "=r"(r[2]), "=r"(r[3]) : "r"(addr));
}
__device__ __forceinline__ void ldm_x2(uint32_t* r, uint32_t addr) {
    asm volatile("ldmatrix.sync.aligned.m8n8.x2.shared.b16 {%0,%1}, [%2];"
                 : "=r"(r[0]), "=r"(r[1]) : "r"(addr));
}
__device__ __forceinline__ void ldm_x2t(uint32_t* r, uint32_t addr) {
    asm volatile("ldmatrix.sync.aligned.m8n8.x2.trans.shared.b16 {%0,%1}, [%2];"
                 : "=r"(r[0]), "=r"(r[1]) : "r"(addr));
}
__device__ __forceinline__ void mma16816(float* c, const uint32_t* a, const uint32_t* b) {
    asm volatile(
        "mma.sync.aligned.m16n8k16.row.col.f32.f16.f16.f32 "
        "{%0,%1,%2,%3}, {%4,%5,%6,%7}, {%8,%9}, {%0,%1,%2,%3};"
        : "+f"(c[0]), "+f"(c[1]), "+f"(c[2]), "+f"(c[3])
        : "r"(a[0]), "r"(a[1]), "r"(a[2]), "r"(a[3]), "r"(b[0]), "r"(b[1]));
}

// ---------------- LayerNorm -> fp16 --------------------------------------------
__global__ __launch_bounds__(256)
void ln_h_kernel(const float* __restrict__ x, const float* __restrict__ gamma,
                 const float* __restrict__ beta, __half* __restrict__ oh)
{
    const int row = blockIdx.x;
    const float4* xr = reinterpret_cast<const float4*>(x + (size_t)row * Cn);
    float4 v = xr[threadIdx.x];
    float s  = v.x + v.y + v.z + v.w;
    float ss = v.x*v.x + v.y*v.y + v.z*v.z + v.w*v.w;
    #pragma unroll
    for (int o = 16; o > 0; o >>= 1) {
        s  += __shfl_xor_sync(0xffffffffu, s,  o);
        ss += __shfl_xor_sync(0xffffffffu, ss, o);
    }
    __shared__ float rs[8], rss[8];
    const int w = threadIdx.x >> 5;
    if ((threadIdx.x & 31) == 0) { rs[w] = s; rss[w] = ss; }
    __syncthreads();
    if (threadIdx.x < 32) {
        float ts  = (threadIdx.x < 8) ? rs[threadIdx.x]  : 0.f;
        float tss = (threadIdx.x < 8) ? rss[threadIdx.x] : 0.f;
        #pragma unroll
        for (int o = 4; o > 0; o >>= 1) {
            ts  += __shfl_xor_sync(0xffffffffu, ts,  o);
            tss += __shfl_xor_sync(0xffffffffu, tss, o);
        }
        if (threadIdx.x == 0) {
            float mean = ts * (1.0f/Cn);
            float var  = tss * (1.0f/Cn) - mean*mean;
            rs[0]  = mean;
            rss[0] = rsqrtf(var + 1e-5f);
        }
    }
    __syncthreads();
    const float mean = rs[0], rstd = rss[0];
    const float4 g4 = reinterpret_cast<const float4*>(gamma)[threadIdx.x];
    const float4 b4 = reinterpret_cast<const float4*>(beta )[threadIdx.x];
    uint2 h;
    h.x = pkh2((v.x - mean)*rstd*g4.x + b4.x, (v.y - mean)*rstd*g4.y + b4.y);
    h.y = pkh2((v.z - mean)*rstd*g4.z + b4.z, (v.w - mean)*rstd*g4.w + b4.w);
    *reinterpret_cast<uint2*>(oh + (size_t)row*Cn + threadIdx.x*4) = h;
}

// ---------------- weight transpose: W[K,N] -> Wt[N,K] fp16 ---------------------
__global__ __launch_bounds__(256)
void wt_h_kernel(const float* __restrict__ W, __half* __restrict__ wh, int K, int N)
{
    __shared__ float tile[32][33];
    const int n0 = blockIdx.x * 32, k0 = blockIdx.y * 32;
    const int tx = threadIdx.x & 31, ty = threadIdx.x >> 5;   // 32 x 8
    #pragma unroll
    for (int yy = ty; yy < 32; yy += 8)
        tile[yy][tx] = W[(size_t)(k0 + yy)*N + n0 + tx];
    __syncthreads();
    #pragma unroll
    for (int yy = ty; yy < 32; yy += 8)
        wh[(size_t)(n0 + yy)*K + k0 + tx] = __float2half_rn(tile[tx][yy]);
}

// ---------------- mma.sync fp16 GEMM (static smem 40KB) ------------------------
#define APITCH 80                      // bytes per row (32 fp16 = 64B + 16B pad)
#define TILE_B (128*APITCH)            // 10240 B
#define STG_B  (2*TILE_B)              // A|B = 20480 B ; 2 stages = 40960 B

template<int MODE>
__global__ __launch_bounds__(256)
void tc_gemm(const __half* __restrict__ Ah, const __half* __restrict__ Bh,
             const float* __restrict__ bias, const float* __restrict__ resid,
             float* __restrict__ outF, __half* __restrict__ outH,
             int M, int N, int K)
{
    __shared__ __align__(16) char smem[2*STG_B];
    const uint32_t tb = smem_u32(smem);
    const int tid = threadIdx.x;
    const int wid = tid >> 5, lane = tid & 31;
    const int bm = blockIdx.y << 7, bn = blockIdx.x << 7;
    const int wm = (wid >> 2) * 64;
    const int wn = (wid & 3) * 32;

    float acc[4][4][4];
    #pragma unroll
    for (int i = 0; i < 4; ++i)
        #pragma unroll
        for (int j = 0; j < 4; ++j)
            #pragma unroll
            for (int q = 0; q < 4; ++q) acc[i][j][q] = 0.f;

    auto issue_loads = [&](int c, int s) {
        const uint32_t st = tb + s*STG_B;
        const int kc = c << 5;
        #pragma unroll
        for (int i = 0; i < 2; ++i) {
            const int u = tid + i*256;
            const int row = u >> 2, ch = u & 3;
            const uint32_t so = (uint32_t)(row*APITCH + ch*16);
            cp16(st +          so, Ah + (size_t)(bm + row)*K + kc + ch*8);
            cp16(st + TILE_B + so, Bh + (size_t)(bn + row)*K + kc + ch*8);
        }
        asm volatile("cp.async.commit_group;" ::: "memory");
    };

    const int NK = K >> 5;
    issue_loads(0, 0);
    issue_loads(1, 1);

    const uint32_t a_r = (uint32_t)(wm + (lane & 15)) * APITCH + (lane >> 4) * 16;
    const uint32_t b_r = (uint32_t)(wn + (lane & 7)) * APITCH + ((lane >> 3) & 1) * 16;

    for (int c = 0; c < NK; ++c) {
        const int s = c & 1;
        if (c + 1 < NK) asm volatile("cp.async.wait_group 1;" ::: "memory");
        else            asm volatile("cp.async.wait_group 0;" ::: "memory");
        __syncthreads();
        const uint32_t st = tb + s*STG_B;

        #pragma unroll
        for (int ks = 0; ks < 2; ++ks) {
            const uint32_t ko = ks * 32;
            uint32_t a[4][4], b[4][2];
            #pragma unroll
            for (int nf = 0; nf < 4; ++nf)
                ldm_x2(b[nf], st + TILE_B + b_r + ko + nf*8*APITCH);
            #pragma unroll
            for (int mf = 0; mf < 4; ++mf)
                ldm_x4(a[mf], st + a_r + ko + mf*16*APITCH);
            #pragma unroll
            for (int mf = 0; mf < 4; ++mf)
                #pragma unroll
                for (int nf = 0; nf < 4; ++nf)
                    mma16816(acc[mf][nf], a[mf], b[nf]);
        }
        __syncthreads();
        if (c + 2 < NK) issue_loads(c + 2, s);
    }

    const int qr = lane >> 2, qc = (lane & 3) * 2;
    #pragma unroll
    for (int mf = 0; mf < 4; ++mf) {
        #pragma unroll
        for (int half_ = 0; half_ < 2; ++half_) {
            const int r = bm + wm + mf*16 + qr + half_*8;
            #pragma unroll
            for (int nf = 0; nf < 4; ++nf) {
                const int n = bn + wn + nf*8 + qc;
                float c0 = acc[mf][nf][half_*2+0] + bias[n];
                float c1 = acc[mf][nf][half_*2+1] + bias[n+1];
                const size_t go = (size_t)r*N + n;
                if (MODE == 1) {
                    const float2 rr = *reinterpret_cast<const float2*>(&resid[go]);
                    c0 += rr.x; c1 += rr.y;
                }
                if (MODE == 2) {
                    c0 = fmaxf(c0, 0.f); c1 = fmaxf(c1, 0.f);
                    *reinterpret_cast<uint32_t*>(outH + go) = pkh2(c0, c1);
                } else {
                    float2 o; o.x = c0; o.y = c1;
                    *reinterpret_cast<float2*>(&outF[go]) = o;
                }
            }
        }
    }
}

// ---------------- Flash attention (fp16 mma, fp32 softmax/accum) ---------------
// Block 128 thr (4 warps), 64 q-rows per block, 64-key tiles.
#define HPITCH 72                       // fp16 elements per smem row (144 B)
#define HPITCHB 144

__global__ __launch_bounds__(128)
void attn_h_kernel(const float* __restrict__ qkv, const int* __restrict__ seq_ls,
                   __half* __restrict__ yh)
{
    const int qt = blockIdx.x, h = blockIdx.y, b = blockIdx.z;

    __shared__ __align__(16) __half Qs[64*HPITCH];
    __shared__ __align__(16) __half Ks[64*HPITCH];
    __shared__ __align__(16) __half Vs[64*HPITCH];

    const int tid = threadIdx.x;
    const int wid = tid >> 5, lane = tid & 31;
    const int wm16 = wid * 16;
    const int seq_l = seq_ls[b];
    const int q0 = b*Tn + qt*64;
    const int kvoff = h*HDd;

    // Load + scale Q (fp32 -> fp16): 64 rows x 64 cols; thread: row tid>>1, 32 cols
    {
        const int r = tid >> 1, c0 = (tid & 1) * 32;
        const float* src = qkv + (size_t)(q0 + r)*3*Cn + kvoff + c0;
        __half* dst = Qs + r*HPITCH + c0;
        #pragma unroll
        for (int i = 0; i < 8; ++i) {
            float4 v = *reinterpret_cast<const float4*>(src + i*4);
            uint2 hh;
            hh.x = pkh2(v.x*0.125f, v.y*0.125f);
            hh.y = pkh2(v.z*0.125f, v.w*0.125f);
            *reinterpret_cast<uint2*>(dst + i*4) = hh;
        }
    }

    const uint32_t qs = smem_u32(Qs), ks_ = smem_u32(Ks), vs = smem_u32(Vs);
    const uint32_t a_r  = (uint32_t)(wm16 + (lane & 15)) * HPITCHB + (lane >> 4) * 16;
    const uint32_t bk_r = (uint32_t)(lane & 7) * HPITCHB + ((lane >> 3) & 1) * 16;
    const uint32_t bv_r = (uint32_t)(lane & 15) * HPITCHB;

    float m0 = -3.0e38f, m1 = -3.0e38f, l0 = 0.f, l1 = 0.f;
    float acc_o[8][4];
    #pragma unroll
    for (int nf = 0; nf < 8; ++nf)
        #pragma unroll
        for (int q = 0; q < 4; ++q) acc_o[nf][q] = 0.f;

    const int tc2 = (lane & 3) * 2;
    const int nkt = (seq_l + 63) >> 6;

    for (int kb = 0; kb < nkt; ++kb) {
        const int kbase = kb << 6;
        __syncthreads();
        // Load K,V tiles (fp32 -> fp16)
        {
            const int r = tid >> 1, c0 = (tid & 1) * 32;
            const float* srcK = qkv + (size_t)(b*Tn + kbase + r)*3*Cn + Cn   + kvoff + c0;
            const float* srcV = qkv + (size_t)(b*Tn + kbase + r)*3*Cn + 2*Cn + kvoff + c0;
            __half* dK = Ks + r*HPITCH + c0;
            __half* dV = Vs + r*HPITCH + c0;
            #pragma unroll
            for (int i = 0; i < 8; ++i) {
                float4 vk = *reinterpret_cast<const float4*>(srcK + i*4);
                float4 vv = *reinterpret_cast<const float4*>(srcV + i*4);
                uint2 hk, hv;
                hk.x = pkh2(vk.x, vk.y); hk.y = pkh2(vk.z, vk.w);
                hv.x = pkh2(vv.x, vv.y); hv.y = pkh2(vv.z, vv.w);
                *reinterpret_cast<uint2*>(dK + i*4) = hk;
                *reinterpret_cast<uint2*>(dV + i*4) = hv;
            }
        }
        __syncthreads();

        // ---- S = Q K^T (64x64 per block; this warp: 16x64) ----
        float sacc[8][4];
        #pragma unroll
        for (int nf = 0; nf < 8; ++nf)
            #pragma unroll
            for (int q = 0; q < 4; ++q) sacc[nf][q] = 0.f;
        #pragma unroll
        for (int ksid = 0; ksid < 4; ++ksid) {
            uint32_t a[4];
            ldm_x4(a, qs + a_r + ksid*32);
            #pragma unroll
            for (int nf = 0; nf < 8; ++nf) {
                uint32_t bb[2];
                ldm_x2(bb, ks_ + bk_r + nf*8*HPITCHB + ksid*32);
                mma16816(sacc[nf], a, bb);
            }
        }

        // ---- mask invalid keys ----
        #pragma unroll
        for (int nf = 0; nf < 8; ++nf) {
            const int kc = kbase + nf*8 + tc2;
            if (kc     >= seq_l) { sacc[nf][0] = -1.0e30f; sacc[nf][2] = -1.0e30f; }
            if (kc + 1 >= seq_l) { sacc[nf][1] = -1.0e30f; sacc[nf][3] = -1.0e30f; }
        }

        // ---- online softmax (rows g=lane>>2 and g+8) ----
        float mx0 = -3.0e38f, mx1 = -3.0e38f;
        #pragma unroll
        for (int nf = 0; nf < 8; ++nf) {
            mx0 = fmaxf(mx0, fmaxf(sacc[nf][0], sacc[nf][1]));
            mx1 = fmaxf(mx1, fmaxf(sacc[nf][2], sacc[nf][3]));
        }
        mx0 = fmaxf(mx0, __shfl_xor_sync(0xffffffffu, mx0, 1));
        mx0 = fmaxf(mx0, __shfl_xor_sync(0xffffffffu, mx0, 2));
        mx1 = fmaxf(mx1, __shfl_xor_sync(0xffffffffu, mx1, 1));
        mx1 = fmaxf(mx1, __shfl_xor_sync(0xffffffffu, mx1, 2));
        const float mn0 = fmaxf(m0, mx0), mn1 = fmaxf(m1, mx1);
        const float f0 = __expf(m0 - mn0), f1 = __expf(m1 - mn1);
        float s0 = 0.f, s1 = 0.f;
        #pragma unroll
        for (int nf = 0; nf < 8; ++nf) {
            sacc[nf][0] = __expf(sacc[nf][0] - mn0);
            sacc[nf][1] = __expf(sacc[nf][1] - mn0);
            sacc[nf][2] = __expf(sacc[nf][2] - mn1);
            sacc[nf][3] = __expf(sacc[nf][3] - mn1);
            s0 += sacc[nf][0] + sacc[nf][1];
            s1 += sacc[nf][2] + sacc[nf][3];
        }
        s0 += __shfl_xor_sync(0xffffffffu, s0, 1);
        s0 += __shfl_xor_sync(0xffffffffu, s0, 2);
        s1 += __shfl_xor_sync(0xffffffffu, s1, 1);
        s1 += __shfl_xor_sync(0xffffffffu, s1, 2);
        m0 = mn0; m1 = mn1;
        l0 = l0*f0 + s0; l1 = l1*f1 + s1;
        #pragma unroll
        for (int nf = 0; nf < 8; ++nf) {
            acc_o[nf][0] *= f0; acc_o[nf][1] *= f0;
            acc_o[nf][2] *= f1; acc_o[nf][3] *= f1;
        }

        // ---- O += P @ V  (P fragments repacked from sacc; V via ldmatrix.trans) --
        #pragma unroll
        for (int ksid = 0; ksid < 4; ++ksid) {
            uint32_t a[4];
            a[0] = pkh2(sacc[2*ksid  ][0], sacc[2*ksid  ][1]);
            a[1] = pkh2(sacc[2*ksid  ][2], sacc[2*ksid  ][3]);
            a[2] = pkh2(sacc[2*ksid+1][0], sacc[2*ksid+1][1]);
            a[3] = pkh2(sacc[2*ksid+1][2], sacc[2*ksid+1][3]);
            #pragma unroll
            for (int nf = 0; nf < 8; ++nf) {
                uint32_t bb[2];
                ldm_x2t(bb, vs + bv_r + ksid*16*HPITCHB + nf*16);
                mma16816(acc_o[nf], a, bb);
            }
        }
    }

    // ---- epilogue: O / l -> fp16 ----
    const float inv0 = 1.0f / l0, inv1 = 1.0f / l1;
    const int g = lane >> 2;
    #pragma unroll
    for (int nf = 0; nf < 8; ++nf) {
        const int col = kvoff + nf*8 + tc2;
        const size_t r0o = (size_t)(q0 + wm16 + g)*Cn + col;
        const size_t r1o = (size_t)(q0 + wm16 + g + 8)*Cn + col;
        *reinterpret_cast<uint32_t*>(yh + r0o) = pkh2(acc_o[nf][0]*inv0, acc_o[nf][1]*inv0);
        *reinterpret_cast<uint32_t*>(yh + r1o) = pkh2(acc_o[nf][2]*inv1, acc_o[nf][3]*inv1);
    }
}

// ---------------- launch ------------------------------------------------------
extern "C" void kernel_launch(void* const* d_in, const int* in_sizes, int n_in,
                              void* d_out, int out_size)
{
    const float* x      = (const float*)d_in[0];
    const int*   seq_ls = (const int*)  d_in[1];
    const float* ln1_g  = (const float*)d_in[2];
    const float* ln1_b  = (const float*)d_in[3];
    const float* w_qkv  = (const float*)d_in[4];
    const float* b_qkv  = (const float*)d_in[5];
    const float* w_proj = (const float*)d_in[6];
    const float* b_proj = (const float*)d_in[7];
    const float* ln2_g  = (const float*)d_in[8];
    const float* ln2_b  = (const float*)d_in[9];
    const float* w_fc   = (const float*)d_in[10];
    const float* b_fc   = (const float*)d_in[11];
    const float* w_fc2  = (const float*)d_in[12];
    const float* b_fc2  = (const float*)d_in[13];
    float* out = (float*)d_out;

    float *qkv, *x1;
    __half *ah, *yh, *ffh, *wh;
    cudaGetSymbolAddress((void**)&qkv, g_qkv);
    cudaGetSymbolAddress((void**)&x1,  g_x1);
    cudaGetSymbolAddress((void**)&ah,  g_ah);
    cudaGetSymbolAddress((void**)&yh,  g_yh);
    cudaGetSymbolAddress((void**)&ffh, g_ffh);
    cudaGetSymbolAddress((void**)&wh,  g_wh);

    // 0. transpose weights -> [N,K] fp16
    wt_h_kernel<<<dim3(3*Cn/32, Cn/32), 256>>>(w_qkv,  wh+OFF_QKV,  Cn,  3*Cn);
    wt_h_kernel<<<dim3(Cn/32,   Cn/32), 256>>>(w_proj, wh+OFF_PROJ, Cn,  Cn);
    wt_h_kernel<<<dim3(FFf/32,  Cn/32), 256>>>(w_fc,   wh+OFF_FC,   Cn,  FFf);
    wt_h_kernel<<<dim3(Cn/32,  FFf/32), 256>>>(w_fc2,  wh+OFF_FC2,  FFf, Cn);

    // 1. LN1 -> fp16
    ln_h_kernel<<<MROWS, 256>>>(x, ln1_g, ln1_b, ah);
    // 2. QKV projection (fp32 out for attention)
    tc_gemm<0><<<dim3(3*Cn/128, MROWS/128), 256>>>(
        ah, wh+OFF_QKV, b_qkv, nullptr, qkv, nullptr, MROWS, 3*Cn, Cn);
    // 3. Attention (fp16 tensor cores) -> y fp16
    attn_h_kernel<<<dim3(Tn/64, NHh, Bn), 128>>>(qkv, seq_ls, yh);
    // 4. proj + residual(x) -> x1 (fp32)
    tc_gemm<1><<<dim3(Cn/128, MROWS/128), 256>>>(
        yh, wh+OFF_PROJ, b_proj, x, x1, nullptr, MROWS, Cn, Cn);
    // 5. LN2 -> fp16
    ln_h_kernel<<<MROWS, 256>>>(x1, ln2_g, ln2_b, ah);
    // 6. FC + ReLU -> ff fp16
    tc_gemm<2><<<dim3(FFf/128, MROWS/128), 256>>>(
        ah, wh+OFF_FC, b_fc, nullptr, nullptr, ffh, MROWS, FFf, Cn);
    // 7. FC2 + residual(x1) -> out
    tc_gemm<1><<<dim3(Cn/128, MROWS/128), 256>>>(
        ffh, wh+OFF_FC2, b_fc2, x1, out, nullptr, MROWS, Cn, FFf);
}

// round 12
// speedup vs baseline: 5.6354x; 1.1020x over previous
#include <cuda_runtime.h>
#include <cuda_fp16.h>
#include <cstdint>
#include <math.h>

// Problem dims (fixed)
#define Bn 8
#define Tn 1024
#define Cn 1024
#define NHh 16
#define HDd 64
#define FFf 4096
#define MROWS (Bn*Tn)   // 8192

// Weight offsets inside the packed transposed-weight buffer (elements)
#define OFF_QKV 0
#define OFF_PROJ (3*Cn*Cn)
#define OFF_FC   (OFF_PROJ + Cn*Cn)
#define OFF_FC2  (OFF_FC + (size_t)FFf*Cn)
#define WSUM     (OFF_FC2 + (size_t)Cn*FFf)

// ---------------- scratch (static device globals; no allocation) -------------
static __device__ __align__(16) __half  g_qkvh[(size_t)MROWS*3*Cn]; // 48 MB
static __device__ __align__(16) float   g_x1 [(size_t)MROWS*Cn];    // 32 MB
static __device__ __align__(16) __half  g_ah [(size_t)MROWS*Cn];    // LN out fp16
static __device__ __align__(16) __half  g_yh [(size_t)MROWS*Cn];    // attn out fp16
static __device__ __align__(16) __half  g_ffh[(size_t)MROWS*FFf];   // relu(fc) fp16
static __device__ __align__(16) __half  g_wh [WSUM];                // W^T fp16

// ---------------- small helpers ------------------------------------------------
__device__ __forceinline__ uint32_t smem_u32(const void* p) {
    uint32_t a;
    asm("{ .reg .u64 t; cvta.to.shared.u64 t, %1; cvt.u32.u64 %0, t; }" : "=r"(a) : "l"(p));
    return a;
}
__device__ __forceinline__ void cp16(uint32_t dst, const void* src) {
    asm volatile("cp.async.cg.shared.global [%0], [%1], 16;" :: "r"(dst), "l"(src) : "memory");
}
__device__ __forceinline__ uint32_t pkh2(float a, float b) {
    __half2 t = __floats2half2_rn(a, b);
    return *reinterpret_cast<uint32_t*>(&t);
}
__device__ __forceinline__ void ldm_x4(uint32_t* r, uint32_t addr) {
    asm volatile("ldmatrix.sync.aligned.m8n8.x4.shared.b16 {%0,%1,%2,%3}, [%4];"
                 : "=r"(r[0]), "=r"(r[1]), "=r"(r[2]), "=r"(r[3]) : "r"(addr));
}
__device__ __forceinline__ void ldm_x2(uint32_t* r, uint32_t addr) {
    asm volatile("ldmatrix.sync.aligned.m8n8.x2.shared.b16 {%0,%1}, [%2];"
                 : "=r"(r[0]), "=r"(r[1]) : "r"(addr));
}
__device__ __forceinline__ void ldm_x2t(uint32_t* r, uint32_t addr) {
    asm volatile("ldmatrix.sync.aligned.m8n8.x2.trans.shared.b16 {%0,%1}, [%2];"
                 : "=r"(r[0]), "=r"(r[1]) : "r"(addr));
}
__device__ __forceinline__ void mma16816(float* c, const uint32_t* a, const uint32_t* b) {
    asm volatile(
        "mma.sync.aligned.m16n8k16.row.col.f32.f16.f16.f32 "
        "{%0,%1,%2,%3}, {%4,%5,%6,%7}, {%8,%9}, {%0,%1,%2,%3};"
        : "+f"(c[0]), "+f"(c[1]), "+f"(c[2]), "+f"(c[3])
        : "r"(a[0]), "r"(a[1]), "r"(a[2]), "r"(a[3]), "r"(b[0]), "r"(b[1]));
}

// ---------------- LayerNorm -> fp16 --------------------------------------------
__global__ __launch_bounds__(256)
void ln_h_kernel(const float* __restrict__ x, const float* __restrict__ gamma,
                 const float* __restrict__ beta, __half* __restrict__ oh)
{
    const int row = blockIdx.x;
    const float4* xr = reinterpret_cast<const float4*>(x + (size_t)row * Cn);
    float4 v = xr[threadIdx.x];
    float s  = v.x + v.y + v.z + v.w;
    float ss = v.x*v.x + v.y*v.y + v.z*v.z + v.w*v.w;
    #pragma unroll
    for (int o = 16; o > 0; o >>= 1) {
        s  += __shfl_xor_sync(0xffffffffu, s,  o);
        ss += __shfl_xor_sync(0xffffffffu, ss, o);
    }
    __shared__ float rs[8], rss[8];
    const int w = threadIdx.x >> 5;
    if ((threadIdx.x & 31) == 0) { rs[w] = s; rss[w] = ss; }
    __syncthreads();
    if (threadIdx.x < 32) {
        float ts  = (threadIdx.x < 8) ? rs[threadIdx.x]  : 0.f;
        float tss = (threadIdx.x < 8) ? rss[threadIdx.x] : 0.f;
        #pragma unroll
        for (int o = 4; o > 0; o >>= 1) {
            ts  += __shfl_xor_sync(0xffffffffu, ts,  o);
            tss += __shfl_xor_sync(0xffffffffu, tss, o);
        }
        if (threadIdx.x == 0) {
            float mean = ts * (1.0f/Cn);
            float var  = tss * (1.0f/Cn) - mean*mean;
            rs[0]  = mean;
            rss[0] = rsqrtf(var + 1e-5f);
        }
    }
    __syncthreads();
    const float mean = rs[0], rstd = rss[0];
    const float4 g4 = reinterpret_cast<const float4*>(gamma)[threadIdx.x];
    const float4 b4 = reinterpret_cast<const float4*>(beta )[threadIdx.x];
    uint2 h;
    h.x = pkh2((v.x - mean)*rstd*g4.x + b4.x, (v.y - mean)*rstd*g4.y + b4.y);
    h.y = pkh2((v.z - mean)*rstd*g4.z + b4.z, (v.w - mean)*rstd*g4.w + b4.w);
    *reinterpret_cast<uint2*>(oh + (size_t)row*Cn + threadIdx.x*4) = h;
}

// ---------------- weight transpose: W[K,N] -> Wt[N,K] fp16 ---------------------
__global__ __launch_bounds__(256)
void wt_h_kernel(const float* __restrict__ W, __half* __restrict__ wh, int K, int N)
{
    __shared__ float tile[32][33];
    const int n0 = blockIdx.x * 32, k0 = blockIdx.y * 32;
    const int tx = threadIdx.x & 31, ty = threadIdx.x >> 5;   // 32 x 8
    #pragma unroll
    for (int yy = ty; yy < 32; yy += 8)
        tile[yy][tx] = W[(size_t)(k0 + yy)*N + n0 + tx];
    __syncthreads();
    #pragma unroll
    for (int yy = ty; yy < 32; yy += 8)
        wh[(size_t)(n0 + yy)*K + k0 + tx] = __float2half_rn(tile[tx][yy]);
}

// ---------------- mma.sync fp16 GEMM (4 warps, 64x64 warp tile) ----------------
// C = A @ B^T : A [M,K] fp16 row-major, B rows = Wt[N,K] fp16.
// Block 128x128, BK=32, 4 warps (2x2), warp tile 64x64, double-buffered cp.async.
// MODE 0: outH = C+bias (fp16) ; MODE 1: outF = C+bias+resid (fp32) ;
// MODE 2: relu(C+bias) -> fp16
#define APITCH 80                      // bytes per row (32 fp16 = 64B + 16B pad)
#define TILE_B (128*APITCH)            // 10240 B
#define STG_B  (2*TILE_B)              // A|B = 20480 B ; 2 stages = 40960 B

template<int MODE>
__global__ __launch_bounds__(128, 2)
void tc_gemm(const __half* __restrict__ Ah, const __half* __restrict__ Bh,
             const float* __restrict__ bias, const float* __restrict__ resid,
             float* __restrict__ outF, __half* __restrict__ outH,
             int M, int N, int K)
{
    __shared__ __align__(16) char smem[2*STG_B];
    const uint32_t tb = smem_u32(smem);
    const int tid = threadIdx.x;
    const int wid = tid >> 5, lane = tid & 31;
    const int bm = blockIdx.y << 7, bn = blockIdx.x << 7;
    const int wm = (wid >> 1) * 64;      // warp M offset (0/64)
    const int wn = (wid & 1) * 64;       // warp N offset (0/64)

    float acc[4][8][4];
    #pragma unroll
    for (int i = 0; i < 4; ++i)
        #pragma unroll
        for (int j = 0; j < 8; ++j)
            #pragma unroll
            for (int q = 0; q < 4; ++q) acc[i][j][q] = 0.f;

    // loads: per tile 128 rows x 4 chunks(16B) = 512 units; 128 thr x 4
    auto issue_loads = [&](int c, int s) {
        const uint32_t st = tb + s*STG_B;
        const int kc = c << 5;
        #pragma unroll
        for (int i = 0; i < 4; ++i) {
            const int u = tid + i*128;
            const int row = u >> 2, ch = u & 3;
            const uint32_t so = (uint32_t)(row*APITCH + ch*16);
            cp16(st +          so, Ah + (size_t)(bm + row)*K + kc + ch*8);
            cp16(st + TILE_B + so, Bh + (size_t)(bn + row)*K + kc + ch*8);
        }
        asm volatile("cp.async.commit_group;" ::: "memory");
    };

    const int NK = K >> 5;
    issue_loads(0, 0);
    issue_loads(1, 1);

    // A-style addressing for both A and B (x4: lane&15 -> row, lane>>4 -> k-half)
    const uint32_t a_r = (uint32_t)(wm + (lane & 15)) * APITCH + (lane >> 4) * 16;
    const uint32_t b_r = (uint32_t)(wn + (lane & 15)) * APITCH + (lane >> 4) * 16;

    for (int c = 0; c < NK; ++c) {
        const int s = c & 1;
        if (c + 1 < NK) asm volatile("cp.async.wait_group 1;" ::: "memory");
        else            asm volatile("cp.async.wait_group 0;" ::: "memory");
        __syncthreads();
        const uint32_t st = tb + s*STG_B;

        #pragma unroll
        for (int ks = 0; ks < 2; ++ks) {
            const uint32_t ko = ks * 32;
            uint32_t a[4][4], b4[4][4];
            #pragma unroll
            for (int mf = 0; mf < 4; ++mf)
                ldm_x4(a[mf], st + a_r + ko + mf*16*APITCH);
            #pragma unroll
            for (int nb = 0; nb < 4; ++nb)
                ldm_x4(b4[nb], st + TILE_B + b_r + ko + nb*16*APITCH);
            #pragma unroll
            for (int mf = 0; mf < 4; ++mf)
                #pragma unroll
                for (int nb = 0; nb < 4; ++nb) {
                    uint32_t bb0[2] = { b4[nb][0], b4[nb][2] };   // n8 tile 2*nb
                    uint32_t bb1[2] = { b4[nb][1], b4[nb][3] };   // n8 tile 2*nb+1
                    mma16816(acc[mf][2*nb],   a[mf], bb0);
                    mma16816(acc[mf][2*nb+1], a[mf], bb1);
                }
        }
        __syncthreads();
        if (c + 2 < NK) issue_loads(c + 2, s);
    }

    // -------- epilogue: fragments direct to global ----------------------------
    const int qr = lane >> 2, qc = (lane & 3) * 2;
    #pragma unroll
    for (int mf = 0; mf < 4; ++mf) {
        #pragma unroll
        for (int half_ = 0; half_ < 2; ++half_) {
            const int r = bm + wm + mf*16 + qr + half_*8;
            #pragma unroll
            for (int nf = 0; nf < 8; ++nf) {
                const int n = bn + wn + nf*8 + qc;
                float c0 = acc[mf][nf][half_*2+0] + bias[n];
                float c1 = acc[mf][nf][half_*2+1] + bias[n+1];
                const size_t go = (size_t)r*N + n;
                if (MODE == 1) {
                    const float2 rr = *reinterpret_cast<const float2*>(&resid[go]);
                    c0 += rr.x; c1 += rr.y;
                    float2 o; o.x = c0; o.y = c1;
                    *reinterpret_cast<float2*>(&outF[go]) = o;
                } else if (MODE == 2) {
                    c0 = fmaxf(c0, 0.f); c1 = fmaxf(c1, 0.f);
                    *reinterpret_cast<uint32_t*>(outH + go) = pkh2(c0, c1);
                } else {
                    *reinterpret_cast<uint32_t*>(outH + go) = pkh2(c0, c1);
                }
            }
        }
    }
}

// ---------------- Flash attention (fp16 in/out, fp32 softmax/accum) ------------
// Block 128 thr (4 warps), 64 q-rows per block, 64-key tiles. qkv is fp16.
#define HPITCH 72                       // fp16 elements per smem row (144 B)
#define HPITCHB 144

__global__ __launch_bounds__(128)
void attn_h_kernel(const __half* __restrict__ qkvh, const int* __restrict__ seq_ls,
                   __half* __restrict__ yh)
{
    const int qt = blockIdx.x, h = blockIdx.y, b = blockIdx.z;

    __shared__ __align__(16) __half Qs[64*HPITCH];
    __shared__ __align__(16) __half Ks[64*HPITCH];
    __shared__ __align__(16) __half Vs[64*HPITCH];

    const int tid = threadIdx.x;
    const int wid = tid >> 5, lane = tid & 31;
    const int wm16 = wid * 16;
    const int seq_l = seq_ls[b];
    const int q0 = b*Tn + qt*64;
    const int kvoff = h*HDd;

    // Load Q tile (fp16 direct, 16B vector copies)
    {
        const int r = tid >> 1, c0 = (tid & 1) * 32;
        const __half* src = qkvh + (size_t)(q0 + r)*3*Cn + kvoff + c0;
        __half* dst = Qs + r*HPITCH + c0;
        #pragma unroll
        for (int i = 0; i < 4; ++i)
            *reinterpret_cast<uint4*>(dst + i*8) =
                *reinterpret_cast<const uint4*>(src + i*8);
    }

    const uint32_t qs = smem_u32(Qs), ks_ = smem_u32(Ks), vs = smem_u32(Vs);
    const uint32_t a_r  = (uint32_t)(wm16 + (lane & 15)) * HPITCHB + (lane >> 4) * 16;
    const uint32_t bk_r = (uint32_t)(lane & 7) * HPITCHB + ((lane >> 3) & 1) * 16;
    const uint32_t bv_r = (uint32_t)(lane & 15) * HPITCHB;

    float m0 = -3.0e38f, m1 = -3.0e38f, l0 = 0.f, l1 = 0.f;
    float acc_o[8][4];
    #pragma unroll
    for (int nf = 0; nf < 8; ++nf)
        #pragma unroll
        for (int q = 0; q < 4; ++q) acc_o[nf][q] = 0.f;

    const int tc2 = (lane & 3) * 2;
    const int nkt = (seq_l + 63) >> 6;

    for (int kb = 0; kb < nkt; ++kb) {
        const int kbase = kb << 6;
        __syncthreads();
        // Load K,V tiles (fp16 direct)
        {
            const int r = tid >> 1, c0 = (tid & 1) * 32;
            const __half* srcK = qkvh + (size_t)(b*Tn + kbase + r)*3*Cn + Cn   + kvoff + c0;
            const __half* srcV = qkvh + (size_t)(b*Tn + kbase + r)*3*Cn + 2*Cn + kvoff + c0;
            __half* dK = Ks + r*HPITCH + c0;
            __half* dV = Vs + r*HPITCH + c0;
            #pragma unroll
            for (int i = 0; i < 4; ++i) {
                *reinterpret_cast<uint4*>(dK + i*8) =
                    *reinterpret_cast<const uint4*>(srcK + i*8);
                *reinterpret_cast<uint4*>(dV + i*8) =
                    *reinterpret_cast<const uint4*>(srcV + i*8);
            }
        }
        __syncthreads();

        // ---- S = Q K^T (64x64 per block; this warp: 16x64) ----
        float sacc[8][4];
        #pragma unroll
        for (int nf = 0; nf < 8; ++nf)
            #pragma unroll
            for (int q = 0; q < 4; ++q) sacc[nf][q] = 0.f;
        #pragma unroll
        for (int ksid = 0; ksid < 4; ++ksid) {
            uint32_t a[4];
            ldm_x4(a, qs + a_r + ksid*32);
            #pragma unroll
            for (int nf = 0; nf < 8; ++nf) {
                uint32_t bb[2];
                ldm_x2(bb, ks_ + bk_r + nf*8*HPITCHB + ksid*32);
                mma16816(sacc[nf], a, bb);
            }
        }

        // ---- scale (1/sqrt(64)) + mask invalid keys ----
        #pragma unroll
        for (int nf = 0; nf < 8; ++nf) {
            sacc[nf][0] *= 0.125f; sacc[nf][1] *= 0.125f;
            sacc[nf][2] *= 0.125f; sacc[nf][3] *= 0.125f;
            const int kc = kbase + nf*8 + tc2;
            if (kc     >= seq_l) { sacc[nf][0] = -1.0e30f; sacc[nf][2] = -1.0e30f; }
            if (kc + 1 >= seq_l) { sacc[nf][1] = -1.0e30f; sacc[nf][3] = -1.0e30f; }
        }

        // ---- online softmax (rows g=lane>>2 and g+8) ----
        float mx0 = -3.0e38f, mx1 = -3.0e38f;
        #pragma unroll
        for (int nf = 0; nf < 8; ++nf) {
            mx0 = fmaxf(mx0, fmaxf(sacc[nf][0], sacc[nf][1]));
            mx1 = fmaxf(mx1, fmaxf(sacc[nf][2], sacc[nf][3]));
        }
        mx0 = fmaxf(mx0, __shfl_xor_sync(0xffffffffu, mx0, 1));
        mx0 = fmaxf(mx0, __shfl_xor_sync(0xffffffffu, mx0, 2));
        mx1 = fmaxf(mx1, __shfl_xor_sync(0xffffffffu, mx1, 1));
        mx1 = fmaxf(mx1, __shfl_xor_sync(0xffffffffu, mx1, 2));
        const float mn0 = fmaxf(m0, mx0), mn1 = fmaxf(m1, mx1);
        const float f0 = __expf(m0 - mn0), f1 = __expf(m1 - mn1);
        float s0 = 0.f, s1 = 0.f;
        #pragma unroll
        for (int nf = 0; nf < 8; ++nf) {
            sacc[nf][0] = __expf(sacc[nf][0] - mn0);
            sacc[nf][1] = __expf(sacc[nf][1] - mn0);
            sacc[nf][2] = __expf(sacc[nf][2] - mn1);
            sacc[nf][3] = __expf(sacc[nf][3] - mn1);
            s0 += sacc[nf][0] + sacc[nf][1];
            s1 += sacc[nf][2] + sacc[nf][3];
        }
        s0 += __shfl_xor_sync(0xffffffffu, s0, 1);
        s0 += __shfl_xor_sync(0xffffffffu, s0, 2);
        s1 += __shfl_xor_sync(0xffffffffu, s1, 1);
        s1 += __shfl_xor_sync(0xffffffffu, s1, 2);
        m0 = mn0; m1 = mn1;
        l0 = l0*f0 + s0; l1 = l1*f1 + s1;
        #pragma unroll
        for (int nf = 0; nf < 8; ++nf) {
            acc_o[nf][0] *= f0; acc_o[nf][1] *= f0;
            acc_o[nf][2] *= f1; acc_o[nf][3] *= f1;
        }

        // ---- O += P @ V  (P fragments repacked from sacc; V via ldmatrix.trans) --
        #pragma unroll
        for (int ksid = 0; ksid < 4; ++ksid) {
            uint32_t a[4];
            a[0] = pkh2(sacc[2*ksid  ][0], sacc[2*ksid  ][1]);
            a[1] = pkh2(sacc[2*ksid  ][2], sacc[2*ksid  ][3]);
            a[2] = pkh2(sacc[2*ksid+1][0], sacc[2*ksid+1][1]);
            a[3] = pkh2(sacc[2*ksid+1][2], sacc[2*ksid+1][3]);
            #pragma unroll
            for (int nf = 0; nf < 8; ++nf) {
                uint32_t bb[2];
                ldm_x2t(bb, vs + bv_r + ksid*16*HPITCHB + nf*16);
                mma16816(acc_o[nf], a, bb);
            }
        }
    }

    // ---- epilogue: O / l -> fp16 ----
    const float inv0 = 1.0f / l0, inv1 = 1.0f / l1;
    const int g = lane >> 2;
    #pragma unroll
    for (int nf = 0; nf < 8; ++nf) {
        const int col = kvoff + nf*8 + tc2;
        const size_t r0o = (size_t)(q0 + wm16 + g)*Cn + col;
        const size_t r1o = (size_t)(q0 + wm16 + g + 8)*Cn + col;
        *reinterpret_cast<uint32_t*>(yh + r0o) = pkh2(acc_o[nf][0]*inv0, acc_o[nf][1]*inv0);
        *reinterpret_cast<uint32_t*>(yh + r1o) = pkh2(acc_o[nf][2]*inv1, acc_o[nf][3]*inv1);
    }
}

// ---------------- launch ------------------------------------------------------
extern "C" void kernel_launch(void* const* d_in, const int* in_sizes, int n_in,
                              void* d_out, int out_size)
{
    const float* x      = (const float*)d_in[0];
    const int*   seq_ls = (const int*)  d_in[1];
    const float* ln1_g  = (const float*)d_in[2];
    const float* ln1_b  = (const float*)d_in[3];
    const float* w_qkv  = (const float*)d_in[4];
    const float* b_qkv  = (const float*)d_in[5];
    const float* w_proj = (const float*)d_in[6];
    const float* b_proj = (const float*)d_in[7];
    const float* ln2_g  = (const float*)d_in[8];
    const float* ln2_b  = (const float*)d_in[9];
    const float* w_fc   = (const float*)d_in[10];
    const float* b_fc   = (const float*)d_in[11];
    const float* w_fc2  = (const float*)d_in[12];
    const float* b_fc2  = (const float*)d_in[13];
    float* out = (float*)d_out;

    float *x1;
    __half *qkvh, *ah, *yh, *ffh, *wh;
    cudaGetSymbolAddress((void**)&qkvh, g_qkvh);
    cudaGetSymbolAddress((void**)&x1,   g_x1);
    cudaGetSymbolAddress((void**)&ah,   g_ah);
    cudaGetSymbolAddress((void**)&yh,   g_yh);
    cudaGetSymbolAddress((void**)&ffh,  g_ffh);
    cudaGetSymbolAddress((void**)&wh,   g_wh);

    // 0. transpose weights -> [N,K] fp16
    wt_h_kernel<<<dim3(3*Cn/32, Cn/32), 256>>>(w_qkv,  wh+OFF_QKV,  Cn,  3*Cn);
    wt_h_kernel<<<dim3(Cn/32,   Cn/32), 256>>>(w_proj, wh+OFF_PROJ, Cn,  Cn);
    wt_h_kernel<<<dim3(FFf/32,  Cn/32), 256>>>(w_fc,   wh+OFF_FC,   Cn,  FFf);
    wt_h_kernel<<<dim3(Cn/32,  FFf/32), 256>>>(w_fc2,  wh+OFF_FC2,  FFf, Cn);

    // 1. LN1 -> fp16
    ln_h_kernel<<<MROWS, 256>>>(x, ln1_g, ln1_b, ah);
    // 2. QKV projection -> fp16 qkv
    tc_gemm<0><<<dim3(3*Cn/128, MROWS/128), 128>>>(
        ah, wh+OFF_QKV, b_qkv, nullptr, nullptr, qkvh, MROWS, 3*Cn, Cn);
    // 3. Attention (fp16 tensor cores) -> y fp16
    attn_h_kernel<<<dim3(Tn/64, NHh, Bn), 128>>>(qkvh, seq_ls, yh);
    // 4. proj + residual(x) -> x1 (fp32)
    tc_gemm<1><<<dim3(Cn/128, MROWS/128), 128>>>(
        yh, wh+OFF_PROJ, b_proj, x, x1, nullptr, MROWS, Cn, Cn);
    // 5. LN2 -> fp16
    ln_h_kernel<<<MROWS, 256>>>(x1, ln2_g, ln2_b, ah);
    // 6. FC + ReLU -> ff fp16
    tc_gemm<2><<<dim3(FFf/128, MROWS/128), 128>>>(
        ah, wh+OFF_FC, b_fc, nullptr, nullptr, ffh, MROWS, FFf, Cn);
    // 7. FC2 + residual(x1) -> out
    tc_gemm<1><<<dim3(Cn/128, MROWS/128), 128>>>(
        ffh, wh+OFF_FC2, b_fc2, x1, out, nullptr, MROWS, Cn, FFf);
}

// round 13
// speedup vs baseline: 6.8618x; 1.2176x over previous
#include <cuda_runtime.h>
#include <cuda_fp16.h>
#include <cstdint>
#include <math.h>

// Problem dims (fixed)
#define Bn 8
#define Tn 1024
#define Cn 1024
#define NHh 16
#define HDd 64
#define FFf 4096
#define MROWS (Bn*Tn)   // 8192

// Weight offsets inside the packed transposed-weight buffer (elements)
#define OFF_QKV 0
#define OFF_PROJ (3*Cn*Cn)
#define OFF_FC   (OFF_PROJ + Cn*Cn)
#define OFF_FC2  (OFF_FC + (size_t)FFf*Cn)
#define WSUM     (OFF_FC2 + (size_t)Cn*FFf)

// ---------------- scratch (static device globals; no allocation) -------------
static __device__ __align__(16) __half  g_qkvh[(size_t)MROWS*3*Cn]; // 48 MB
static __device__ __align__(16) float   g_x1 [(size_t)MROWS*Cn];    // 32 MB
static __device__ __align__(16) __half  g_ah [(size_t)MROWS*Cn];    // LN out fp16
static __device__ __align__(16) __half  g_yh [(size_t)MROWS*Cn];    // attn out fp16
static __device__ __align__(16) __half  g_ffh[(size_t)MROWS*FFf];   // relu(fc) fp16
static __device__ __align__(16) __half  g_wh [WSUM];                // W^T fp16

// ---------------- small helpers ------------------------------------------------
__device__ __forceinline__ uint32_t smem_u32(const void* p) {
    uint32_t a;
    asm("{ .reg .u64 t; cvta.to.shared.u64 t, %1; cvt.u32.u64 %0, t; }" : "=r"(a) : "l"(p));
    return a;
}
__device__ __forceinline__ void cp16(uint32_t dst, const void* src) {
    asm volatile("cp.async.cg.shared.global [%0], [%1], 16;" :: "r"(dst), "l"(src) : "memory");
}
__device__ __forceinline__ uint32_t pkh2(float a, float b) {
    __half2 t = __floats2half2_rn(a, b);
    return *reinterpret_cast<uint32_t*>(&t);
}
__device__ __forceinline__ void ldm_x4(uint32_t* r, uint32_t addr) {
    asm volatile("ldmatrix.sync.aligned.m8n8.x4.shared.b16 {%0,%1,%2,%3}, [%4];"
                 : "=r"(r[0]), "=r"(r[1]), "=r"(r[2]), "=r"(r[3]) : "r"(addr));
}
__device__ __forceinline__ void ldm_x2(uint32_t* r, uint32_t addr) {
    asm volatile("ldmatrix.sync.aligned.m8n8.x2.shared.b16 {%0,%1}, [%2];"
                 : "=r"(r[0]), "=r"(r[1]) : "r"(addr));
}
__device__ __forceinline__ void ldm_x2t(uint32_t* r, uint32_t addr) {
    asm volatile("ldmatrix.sync.aligned.m8n8.x2.trans.shared.b16 {%0,%1}, [%2];"
                 : "=r"(r[0]), "=r"(r[1]) : "r"(addr));
}
__device__ __forceinline__ void mma16816(float* c, const uint32_t* a, const uint32_t* b) {
    asm volatile(
        "mma.sync.aligned.m16n8k16.row.col.f32.f16.f16.f32 "
        "{%0,%1,%2,%3}, {%4,%5,%6,%7}, {%8,%9}, {%0,%1,%2,%3};"
        : "+f"(c[0]), "+f"(c[1]), "+f"(c[2]), "+f"(c[3])
        : "r"(a[0]), "r"(a[1]), "r"(a[2]), "r"(a[3]), "r"(b[0]), "r"(b[1]));
}

// ---------------- LayerNorm -> fp16 --------------------------------------------
__global__ __launch_bounds__(256)
void ln_h_kernel(const float* __restrict__ x, const float* __restrict__ gamma,
                 const float* __restrict__ beta, __half* __restrict__ oh)
{
    const int row = blockIdx.x;
    const float4* xr = reinterpret_cast<const float4*>(x + (size_t)row * Cn);
    float4 v = xr[threadIdx.x];
    float s  = v.x + v.y + v.z + v.w;
    float ss = v.x*v.x + v.y*v.y + v.z*v.z + v.w*v.w;
    #pragma unroll
    for (int o = 16; o > 0; o >>= 1) {
        s  += __shfl_xor_sync(0xffffffffu, s,  o);
        ss += __shfl_xor_sync(0xffffffffu, ss, o);
    }
    __shared__ float rs[8], rss[8];
    const int w = threadIdx.x >> 5;
    if ((threadIdx.x & 31) == 0) { rs[w] = s; rss[w] = ss; }
    __syncthreads();
    if (threadIdx.x < 32) {
        float ts  = (threadIdx.x < 8) ? rs[threadIdx.x]  : 0.f;
        float tss = (threadIdx.x < 8) ? rss[threadIdx.x] : 0.f;
        #pragma unroll
        for (int o = 4; o > 0; o >>= 1) {
            ts  += __shfl_xor_sync(0xffffffffu, ts,  o);
            tss += __shfl_xor_sync(0xffffffffu, tss, o);
        }
        if (threadIdx.x == 0) {
            float mean = ts * (1.0f/Cn);
            float var  = tss * (1.0f/Cn) - mean*mean;
            rs[0]  = mean;
            rss[0] = rsqrtf(var + 1e-5f);
        }
    }
    __syncthreads();
    const float mean = rs[0], rstd = rss[0];
    const float4 g4 = reinterpret_cast<const float4*>(gamma)[threadIdx.x];
    const float4 b4 = reinterpret_cast<const float4*>(beta )[threadIdx.x];
    uint2 h;
    h.x = pkh2((v.x - mean)*rstd*g4.x + b4.x, (v.y - mean)*rstd*g4.y + b4.y);
    h.y = pkh2((v.z - mean)*rstd*g4.z + b4.z, (v.w - mean)*rstd*g4.w + b4.w);
    *reinterpret_cast<uint2*>(oh + (size_t)row*Cn + threadIdx.x*4) = h;
}

// ---------------- weight transpose: W[K,N] -> Wt[N,K] fp16 ---------------------
__global__ __launch_bounds__(256)
void wt_h_kernel(const float* __restrict__ W, __half* __restrict__ wh, int K, int N)
{
    __shared__ float tile[32][33];
    const int n0 = blockIdx.x * 32, k0 = blockIdx.y * 32;
    const int tx = threadIdx.x & 31, ty = threadIdx.x >> 5;   // 32 x 8
    #pragma unroll
    for (int yy = ty; yy < 32; yy += 8)
        tile[yy][tx] = W[(size_t)(k0 + yy)*N + n0 + tx];
    __syncthreads();
    #pragma unroll
    for (int yy = ty; yy < 32; yy += 8)
        wh[(size_t)(n0 + yy)*K + k0 + tx] = __float2half_rn(tile[tx][yy]);
}

// ---------------- mma.sync fp16 GEMM (4 warps, 3-stage swizzled smem) ----------
// C = A @ B^T : A [M,K] fp16 row-major, B rows = Wt[N,K] fp16.
// Block 128x128, BK=32, 4 warps (2x2), warp tile 64x64.
// Rows are 64B; 16B chunk swizzle: phys = ch ^ ((row>>1)&3). Conflict-free ldmatrix.
// 3 stages x 16KB = 48KB static; ONE __syncthreads per chunk.
// MODE 0: outH = C+bias (fp16) ; MODE 1: outF = C+bias+resid (fp32) ;
// MODE 2: relu(C+bias) -> fp16
#define GTILE 8192                      // 128 rows * 64 B
#define GSTG  (2*GTILE)                 // A|B per stage = 16384 B

template<int MODE>
__global__ __launch_bounds__(128, 2)
void tc_gemm(const __half* __restrict__ Ah, const __half* __restrict__ Bh,
             const float* __restrict__ bias, const float* __restrict__ resid,
             float* __restrict__ outF, __half* __restrict__ outH,
             int M, int N, int K)
{
    __shared__ __align__(16) char smem[3*GSTG];   // 49152 B
    const uint32_t tb = smem_u32(smem);
    const int tid = threadIdx.x;
    const int wid = tid >> 5, lane = tid & 31;
    const int bm = blockIdx.y << 7, bn = blockIdx.x << 7;
    const int wm = (wid >> 1) * 64;
    const int wn = (wid & 1) * 64;

    float acc[4][8][4];
    #pragma unroll
    for (int i = 0; i < 4; ++i)
        #pragma unroll
        for (int j = 0; j < 8; ++j)
            #pragma unroll
            for (int q = 0; q < 4; ++q) acc[i][j][q] = 0.f;

    // loads: per stage, 2 tiles x 512 16B-units; 128 thr x 4 per tile
    auto issue_loads = [&](int c, int s) {
        const uint32_t st = tb + s*GSTG;
        const int kc = c << 5;
        #pragma unroll
        for (int i = 0; i < 4; ++i) {
            const int u = tid + i*128;
            const int row = u >> 2, ch = u & 3;
            const uint32_t so = (uint32_t)(row*64 + ((ch ^ ((row>>1)&3)))*16);
            cp16(st +         so, Ah + (size_t)(bm + row)*K + kc + ch*8);
            cp16(st + GTILE + so, Bh + (size_t)(bn + row)*K + kc + ch*8);
        }
        asm volatile("cp.async.commit_group;" ::: "memory");
    };

    const int NK = K >> 5;
    issue_loads(0, 0);
    issue_loads(1, 1);

    // per-lane ldmatrix row bases + swizzle keys
    const int khalf = lane >> 4;
    uint32_t baseA[4], baseB[4];
    uint32_t swA[4], swB[4];
    #pragma unroll
    for (int f = 0; f < 4; ++f) {
        const int rA = wm + (lane & 15) + f*16;
        const int rB = wn + (lane & 15) + f*16;
        baseA[f] = (uint32_t)rA * 64;  swA[f] = (uint32_t)((rA >> 1) & 3);
        baseB[f] = (uint32_t)rB * 64;  swB[f] = (uint32_t)((rB >> 1) & 3);
    }

    int s = 0;
    for (int c = 0; c < NK; ++c) {
        if (c + 1 < NK) asm volatile("cp.async.wait_group 1;" ::: "memory");
        else            asm volatile("cp.async.wait_group 0;" ::: "memory");
        __syncthreads();
        const uint32_t st = tb + s*GSTG;

        #pragma unroll
        for (int ks = 0; ks < 2; ++ks) {
            const uint32_t lch = (uint32_t)(2*ks + khalf);
            uint32_t a[4][4], b4[4][4];
            #pragma unroll
            for (int mf = 0; mf < 4; ++mf)
                ldm_x4(a[mf], st + baseA[mf] + ((lch ^ swA[mf]) << 4));
            #pragma unroll
            for (int nb = 0; nb < 4; ++nb)
                ldm_x4(b4[nb], st + GTILE + baseB[nb] + ((lch ^ swB[nb]) << 4));
            #pragma unroll
            for (int mf = 0; mf < 4; ++mf)
                #pragma unroll
                for (int nb = 0; nb < 4; ++nb) {
                    uint32_t bb0[2] = { b4[nb][0], b4[nb][2] };
                    uint32_t bb1[2] = { b4[nb][1], b4[nb][3] };
                    mma16816(acc[mf][2*nb],   a[mf], bb0);
                    mma16816(acc[mf][2*nb+1], a[mf], bb1);
                }
        }
        // issue loads for chunk c+2 into stage (c+2)%3 = stage freed at iter c-1
        if (c + 2 < NK) {
            int s2 = s + 2; if (s2 >= 3) s2 -= 3;
            issue_loads(c + 2, s2);
        }
        if (++s == 3) s = 0;
    }

    // -------- epilogue: fragments direct to global ----------------------------
    const int qr = lane >> 2, qc = (lane & 3) * 2;
    #pragma unroll
    for (int mf = 0; mf < 4; ++mf) {
        #pragma unroll
        for (int half_ = 0; half_ < 2; ++half_) {
            const int r = bm + wm + mf*16 + qr + half_*8;
            #pragma unroll
            for (int nf = 0; nf < 8; ++nf) {
                const int n = bn + wn + nf*8 + qc;
                float c0 = acc[mf][nf][half_*2+0] + bias[n];
                float c1 = acc[mf][nf][half_*2+1] + bias[n+1];
                const size_t go = (size_t)r*N + n;
                if (MODE == 1) {
                    const float2 rr = *reinterpret_cast<const float2*>(&resid[go]);
                    c0 += rr.x; c1 += rr.y;
                    float2 o; o.x = c0; o.y = c1;
                    *reinterpret_cast<float2*>(&outF[go]) = o;
                } else if (MODE == 2) {
                    c0 = fmaxf(c0, 0.f); c1 = fmaxf(c1, 0.f);
                    *reinterpret_cast<uint32_t*>(outH + go) = pkh2(c0, c1);
                } else {
                    *reinterpret_cast<uint32_t*>(outH + go) = pkh2(c0, c1);
                }
            }
        }
    }
}

// ---------------- Flash attention (fp16, 128 q-rows/block, cp.async K/V) -------
// Block 256 thr (8 warps), 128 q-rows per block, 64-key tiles.
#define HPITCH 72                       // fp16 elements per smem row (144 B)
#define HPITCHB 144

__global__ __launch_bounds__(256)
void attn_h_kernel(const __half* __restrict__ qkvh, const int* __restrict__ seq_ls,
                   __half* __restrict__ yh)
{
    const int qt = blockIdx.x, h = blockIdx.y, b = blockIdx.z;

    __shared__ __align__(16) __half Qs[128*HPITCH];
    __shared__ __align__(16) __half Ks[64*HPITCH];
    __shared__ __align__(16) __half Vs[64*HPITCH];

    const int tid = threadIdx.x;
    const int wid = tid >> 5, lane = tid & 31;
    const int wm16 = wid * 16;
    const int seq_l = seq_ls[b];
    const int q0 = b*Tn + qt*128;
    const int kvoff = h*HDd;

    // Load Q tile (128 rows x 64 fp16; 16B vector copies)
    {
        const int r = tid >> 1, c0 = (tid & 1) * 32;
        const __half* src = qkvh + (size_t)(q0 + r)*3*Cn + kvoff + c0;
        __half* dst = Qs + r*HPITCH + c0;
        #pragma unroll
        for (int i = 0; i < 4; ++i)
            *reinterpret_cast<uint4*>(dst + i*8) =
                *reinterpret_cast<const uint4*>(src + i*8);
    }

    const uint32_t qs = smem_u32(Qs), ks_ = smem_u32(Ks), vs = smem_u32(Vs);
    const uint32_t a_r  = (uint32_t)(wm16 + (lane & 15)) * HPITCHB + (lane >> 4) * 16;
    const uint32_t bk_r = (uint32_t)(lane & 7) * HPITCHB + ((lane >> 3) & 1) * 16;
    const uint32_t bv_r = (uint32_t)(lane & 15) * HPITCHB;

    float m0 = -3.0e38f, m1 = -3.0e38f, l0 = 0.f, l1 = 0.f;
    float acc_o[8][4];
    #pragma unroll
    for (int nf = 0; nf < 8; ++nf)
        #pragma unroll
        for (int q = 0; q < 4; ++q) acc_o[nf][q] = 0.f;

    const int tc2 = (lane & 3) * 2;
    const int nkt = (seq_l + 63) >> 6;

    for (int kb = 0; kb < nkt; ++kb) {
        const int kbase = kb << 6;
        __syncthreads();
        // Load K,V tiles via cp.async (64 rows x 128B each; 2 units/thread/tile)
        {
            #pragma unroll
            for (int i = 0; i < 2; ++i) {
                const int u = tid + i*256;
                const int row = u >> 3, ch = u & 7;
                const uint32_t so = (uint32_t)(row*HPITCHB + ch*16);
                const size_t gb = (size_t)(b*Tn + kbase + row)*3*Cn + kvoff + ch*8;
                cp16(ks_ + so, qkvh + gb + Cn);
                cp16(vs  + so, qkvh + gb + 2*Cn);
            }
            asm volatile("cp.async.commit_group;" ::: "memory");
            asm volatile("cp.async.wait_group 0;" ::: "memory");
        }
        __syncthreads();

        // ---- S = Q K^T (128x64 per block; this warp: 16x64) ----
        float sacc[8][4];
        #pragma unroll
        for (int nf = 0; nf < 8; ++nf)
            #pragma unroll
            for (int q = 0; q < 4; ++q) sacc[nf][q] = 0.f;
        #pragma unroll
        for (int ksid = 0; ksid < 4; ++ksid) {
            uint32_t a[4];
            ldm_x4(a, qs + a_r + ksid*32);
            #pragma unroll
            for (int nf = 0; nf < 8; ++nf) {
                uint32_t bb[2];
                ldm_x2(bb, ks_ + bk_r + nf*8*HPITCHB + ksid*32);
                mma16816(sacc[nf], a, bb);
            }
        }

        // ---- scale (1/sqrt(64)) + mask invalid keys ----
        #pragma unroll
        for (int nf = 0; nf < 8; ++nf) {
            sacc[nf][0] *= 0.125f; sacc[nf][1] *= 0.125f;
            sacc[nf][2] *= 0.125f; sacc[nf][3] *= 0.125f;
            const int kc = kbase + nf*8 + tc2;
            if (kc     >= seq_l) { sacc[nf][0] = -1.0e30f; sacc[nf][2] = -1.0e30f; }
            if (kc + 1 >= seq_l) { sacc[nf][1] = -1.0e30f; sacc[nf][3] = -1.0e30f; }
        }

        // ---- online softmax (rows g=lane>>2 and g+8) ----
        float mx0 = -3.0e38f, mx1 = -3.0e38f;
        #pragma unroll
        for (int nf = 0; nf < 8; ++nf) {
            mx0 = fmaxf(mx0, fmaxf(sacc[nf][0], sacc[nf][1]));
            mx1 = fmaxf(mx1, fmaxf(sacc[nf][2], sacc[nf][3]));
        }
        mx0 = fmaxf(mx0, __shfl_xor_sync(0xffffffffu, mx0, 1));
        mx0 = fmaxf(mx0, __shfl_xor_sync(0xffffffffu, mx0, 2));
        mx1 = fmaxf(mx1, __shfl_xor_sync(0xffffffffu, mx1, 1));
        mx1 = fmaxf(mx1, __shfl_xor_sync(0xffffffffu, mx1, 2));
        const float mn0 = fmaxf(m0, mx0), mn1 = fmaxf(m1, mx1);
        const float f0 = __expf(m0 - mn0), f1 = __expf(m1 - mn1);
        float s0 = 0.f, s1 = 0.f;
        #pragma unroll
        for (int nf = 0; nf < 8; ++nf) {
            sacc[nf][0] = __expf(sacc[nf][0] - mn0);
            sacc[nf][1] = __expf(sacc[nf][1] - mn0);
            sacc[nf][2] = __expf(sacc[nf][2] - mn1);
            sacc[nf][3] = __expf(sacc[nf][3] - mn1);
            s0 += sacc[nf][0] + sacc[nf][1];
            s1 += sacc[nf][2] + sacc[nf][3];
        }
        s0 += __shfl_xor_sync(0xffffffffu, s0, 1);
        s0 += __shfl_xor_sync(0xffffffffu, s0, 2);
        s1 += __shfl_xor_sync(0xffffffffu, s1, 1);
        s1 += __shfl_xor_sync(0xffffffffu, s1, 2);
        m0 = mn0; m1 = mn1;
        l0 = l0*f0 + s0; l1 = l1*f1 + s1;
        #pragma unroll
        for (int nf = 0; nf < 8; ++nf) {
            acc_o[nf][0] *= f0; acc_o[nf][1] *= f0;
            acc_o[nf][2] *= f1; acc_o[nf][3] *= f1;
        }

        // ---- O += P @ V (P repacked from sacc; V via ldmatrix.trans) ----
        #pragma unroll
        for (int ksid = 0; ksid < 4; ++ksid) {
            uint32_t a[4];
            a[0] = pkh2(sacc[2*ksid  ][0], sacc[2*ksid  ][1]);
            a[1] = pkh2(sacc[2*ksid  ][2], sacc[2*ksid  ][3]);
            a[2] = pkh2(sacc[2*ksid+1][0], sacc[2*ksid+1][1]);
            a[3] = pkh2(sacc[2*ksid+1][2], sacc[2*ksid+1][3]);
            #pragma unroll
            for (int nf = 0; nf < 8; ++nf) {
                uint32_t bb[2];
                ldm_x2t(bb, vs + bv_r + ksid*16*HPITCHB + nf*16);
                mma16816(acc_o[nf], a, bb);
            }
        }
    }

    // ---- epilogue: O / l -> fp16 ----
    const float inv0 = 1.0f / l0, inv1 = 1.0f / l1;
    const int g = lane >> 2;
    #pragma unroll
    for (int nf = 0; nf < 8; ++nf) {
        const int col = kvoff + nf*8 + tc2;
        const size_t r0o = (size_t)(q0 + wm16 + g)*Cn + col;
        const size_t r1o = (size_t)(q0 + wm16 + g + 8)*Cn + col;
        *reinterpret_cast<uint32_t*>(yh + r0o) = pkh2(acc_o[nf][0]*inv0, acc_o[nf][1]*inv0);
        *reinterpret_cast<uint32_t*>(yh + r1o) = pkh2(acc_o[nf][2]*inv1, acc_o[nf][3]*inv1);
    }
}

// ---------------- launch ------------------------------------------------------
extern "C" void kernel_launch(void* const* d_in, const int* in_sizes, int n_in,
                              void* d_out, int out_size)
{
    const float* x      = (const float*)d_in[0];
    const int*   seq_ls = (const int*)  d_in[1];
    const float* ln1_g  = (const float*)d_in[2];
    const float* ln1_b  = (const float*)d_in[3];
    const float* w_qkv  = (const float*)d_in[4];
    const float* b_qkv  = (const float*)d_in[5];
    const float* w_proj = (const float*)d_in[6];
    const float* b_proj = (const float*)d_in[7];
    const float* ln2_g  = (const float*)d_in[8];
    const float* ln2_b  = (const float*)d_in[9];
    const float* w_fc   = (const float*)d_in[10];
    const float* b_fc   = (const float*)d_in[11];
    const float* w_fc2  = (const float*)d_in[12];
    const float* b_fc2  = (const float*)d_in[13];
    float* out = (float*)d_out;

    float *x1;
    __half *qkvh, *ah, *yh, *ffh, *wh;
    cudaGetSymbolAddress((void**)&qkvh, g_qkvh);
    cudaGetSymbolAddress((void**)&x1,   g_x1);
    cudaGetSymbolAddress((void**)&ah,   g_ah);
    cudaGetSymbolAddress((void**)&yh,   g_yh);
    cudaGetSymbolAddress((void**)&ffh,  g_ffh);
    cudaGetSymbolAddress((void**)&wh,   g_wh);

    // 0. transpose weights -> [N,K] fp16
    wt_h_kernel<<<dim3(3*Cn/32, Cn/32), 256>>>(w_qkv,  wh+OFF_QKV,  Cn,  3*Cn);
    wt_h_kernel<<<dim3(Cn/32,   Cn/32), 256>>>(w_proj, wh+OFF_PROJ, Cn,  Cn);
    wt_h_kernel<<<dim3(FFf/32,  Cn/32), 256>>>(w_fc,   wh+OFF_FC,   Cn,  FFf);
    wt_h_kernel<<<dim3(Cn/32,  FFf/32), 256>>>(w_fc2,  wh+OFF_FC2,  FFf, Cn);

    // 1. LN1 -> fp16
    ln_h_kernel<<<MROWS, 256>>>(x, ln1_g, ln1_b, ah);
    // 2. QKV projection -> fp16 qkv
    tc_gemm<0><<<dim3(3*Cn/128, MROWS/128), 128>>>(
        ah, wh+OFF_QKV, b_qkv, nullptr, nullptr, qkvh, MROWS, 3*Cn, Cn);
    // 3. Attention (fp16 tensor cores, 128-row q tiles) -> y fp16
    attn_h_kernel<<<dim3(Tn/128, NHh, Bn), 256>>>(qkvh, seq_ls, yh);
    // 4. proj + residual(x) -> x1 (fp32)
    tc_gemm<1><<<dim3(Cn/128, MROWS/128), 128>>>(
        yh, wh+OFF_PROJ, b_proj, x, x1, nullptr, MROWS, Cn, Cn);
    // 5. LN2 -> fp16
    ln_h_kernel<<<MROWS, 256>>>(x1, ln2_g, ln2_b, ah);
    // 6. FC + ReLU -> ff fp16
    tc_gemm<2><<<dim3(FFf/128, MROWS/128), 128>>>(
        ah, wh+OFF_FC, b_fc, nullptr, nullptr, ffh, MROWS, FFf, Cn);
    // 7. FC2 + residual(x1) -> out
    tc_gemm<1><<<dim3(Cn/128, MROWS/128), 128>>>(
        ffh, wh+OFF_FC2, b_fc2, x1, out, nullptr, MROWS, Cn, FFf);
}